// round 3
// baseline (speedup 1.0000x reference)
#include <cuda_runtime.h>
#include <math.h>
#include <stdint.h>

#define B_   256
#define T_   64
#define H_   1024
#define V_   128
#define L_   32
#define N4H  4096

// GEMM tiling
#define BM 128
#define BN 64
#define BK 16
#define APAD 20   // A smem row stride (floats): conflict-free for frag reads
#define BPAD 72   // B smem row stride (floats)

// ---------------- persistent device scratch ----------------
__device__ float g_h[B_ * H_];
__device__ float g_c[B_ * H_];
__device__ float g_z[B_ * N4H];
__device__ float g_decEW[V_ * N4H];
__device__ int   g_tok[B_];

// ---------------- helpers ----------------
__device__ __forceinline__ void split_tf32(float x, float& hi, float& lo) {
    uint32_t u;
    asm("cvt.rna.tf32.f32 %0, %1;" : "=r"(u) : "f"(x));
    hi = __uint_as_float(u);
    uint32_t u2;
    float r = x - hi;
    asm("cvt.rna.tf32.f32 %0, %1;" : "=r"(u2) : "f"(r));
    lo = __uint_as_float(u2);
}

__device__ __forceinline__ void mma_tf32(float* d, const float* a, const float* b) {
    asm volatile(
        "mma.sync.aligned.m16n8k8.row.col.f32.tf32.tf32.f32 "
        "{%0,%1,%2,%3}, {%4,%5,%6,%7}, {%8,%9}, {%0,%1,%2,%3};"
        : "+f"(d[0]), "+f"(d[1]), "+f"(d[2]), "+f"(d[3])
        : "r"(__float_as_uint(a[0])), "r"(__float_as_uint(a[1])),
          "r"(__float_as_uint(a[2])), "r"(__float_as_uint(a[3])),
          "r"(__float_as_uint(b[0])), "r"(__float_as_uint(b[1])));
}

// ---------------- tf32-split tensor-core step GEMM ----------------
// Z[m,n] = sum_k A0[bm+m, k] B0[k, n]            (K0 cols)
//        + sum_k A1tbl[rows_s[m], k] B1[k, n]    (K1 cols, gathered rows)
//        + bias[n] + addTbl[addIdx[m], n]
// grid (N4H/BN, M/BM), 256 threads (8 warps; warp grid 4M x 2N, warp tile 32x32)
__global__ __launch_bounds__(256, 1)
void gemm_tc(const float* __restrict__ A0, const float* __restrict__ B0, int K0,
             const float* __restrict__ A1tbl, const int* __restrict__ A1idx, int A1stride,
             const float* __restrict__ B1, int K1,
             const float* __restrict__ bias,
             const float* __restrict__ addTbl, const int* __restrict__ addIdx,
             float* __restrict__ Z)
{
    __shared__ float AsH[BM][APAD];
    __shared__ float AsL[BM][APAD];
    __shared__ float BsH[BK][BPAD];
    __shared__ float BsL[BK][BPAD];
    __shared__ int   rows_s[BM];

    const int tid = threadIdx.x;
    const int wid = tid >> 5;
    const int lid = tid & 31;
    const int gid = lid >> 2;       // 0..7
    const int tig = lid & 3;        // 0..3
    const int bn  = blockIdx.x * BN;
    const int bm  = blockIdx.y * BM;
    const int wm  = (wid & 3) * 32; // warp m offset
    const int wn  = (wid >> 2) * 32;// warp n offset

    if (A1idx && tid < BM) rows_s[tid] = A1idx[(size_t)(bm + tid) * A1stride];
    __syncthreads();

    float acc[2][4][4];
#pragma unroll
    for (int mf = 0; mf < 2; mf++)
#pragma unroll
        for (int nf = 0; nf < 4; nf++)
#pragma unroll
            for (int q = 0; q < 4; q++) acc[mf][nf][q] = 0.f;

    const int nch0 = K0 / BK;
    const int nch  = nch0 + K1 / BK;

    // per-thread load coordinates
    const int am  = tid >> 1;            // A row 0..127
    const int ac0 = (tid & 1) * 8;       // A col base (2 x float4)
    const int bk  = tid >> 4;            // B k-row 0..15
    const int bn4 = (tid & 15) * 4;      // B col base (1 x float4)

    float4 aReg0, aReg1, bReg;

    // prologue: stage chunk 0
    {
        const float* aSrc = (0 < nch0) ? A0 : A1tbl;
        const float* bSrc = (0 < nch0) ? B0 : B1;
        int gath = !(0 < nch0);
        int grow = gath ? rows_s[am] : (bm + am);
        const float* ap = aSrc + (size_t)grow * H_ + ac0;
        aReg0 = *(const float4*)ap;
        aReg1 = *(const float4*)(ap + 4);
        bReg  = *(const float4*)(bSrc + (size_t)bk * N4H + bn + bn4);
    }

    for (int c = 0; c < nch; c++) {
        // ---- split staged regs into smem ----
        {
            float h0, l0;
            split_tf32(aReg0.x, h0, l0); AsH[am][ac0 + 0] = h0; AsL[am][ac0 + 0] = l0;
            split_tf32(aReg0.y, h0, l0); AsH[am][ac0 + 1] = h0; AsL[am][ac0 + 1] = l0;
            split_tf32(aReg0.z, h0, l0); AsH[am][ac0 + 2] = h0; AsL[am][ac0 + 2] = l0;
            split_tf32(aReg0.w, h0, l0); AsH[am][ac0 + 3] = h0; AsL[am][ac0 + 3] = l0;
            split_tf32(aReg1.x, h0, l0); AsH[am][ac0 + 4] = h0; AsL[am][ac0 + 4] = l0;
            split_tf32(aReg1.y, h0, l0); AsH[am][ac0 + 5] = h0; AsL[am][ac0 + 5] = l0;
            split_tf32(aReg1.z, h0, l0); AsH[am][ac0 + 6] = h0; AsL[am][ac0 + 6] = l0;
            split_tf32(aReg1.w, h0, l0); AsH[am][ac0 + 7] = h0; AsL[am][ac0 + 7] = l0;
            split_tf32(bReg.x, h0, l0);  BsH[bk][bn4 + 0] = h0; BsL[bk][bn4 + 0] = l0;
            split_tf32(bReg.y, h0, l0);  BsH[bk][bn4 + 1] = h0; BsL[bk][bn4 + 1] = l0;
            split_tf32(bReg.z, h0, l0);  BsH[bk][bn4 + 2] = h0; BsL[bk][bn4 + 2] = l0;
            split_tf32(bReg.w, h0, l0);  BsH[bk][bn4 + 3] = h0; BsL[bk][bn4 + 3] = l0;
        }
        __syncthreads();

        // ---- stage next chunk (global latency overlaps MMA below) ----
        if (c + 1 < nch) {
            int cc   = c + 1;
            int gath = !(cc < nch0);
            int ck   = (gath ? (cc - nch0) : cc) * BK;
            const float* aSrc = gath ? A1tbl : A0;
            const float* bSrc = gath ? B1 : B0;
            int grow = gath ? rows_s[am] : (bm + am);
            const float* ap = aSrc + (size_t)grow * H_ + ck + ac0;
            aReg0 = *(const float4*)ap;
            aReg1 = *(const float4*)(ap + 4);
            bReg  = *(const float4*)(bSrc + (size_t)(ck + bk) * N4H + bn + bn4);
        }

        // ---- MMA over BK=16: two k8 sub-steps ----
#pragma unroll
        for (int k8 = 0; k8 < BK; k8 += 8) {
            float aH[2][4], aL[2][4], bH[4][2], bL[4][2];
#pragma unroll
            for (int mf = 0; mf < 2; mf++) {
                int r0 = wm + mf * 16 + gid;
                aH[mf][0] = AsH[r0][k8 + tig];     aH[mf][1] = AsH[r0 + 8][k8 + tig];
                aH[mf][2] = AsH[r0][k8 + tig + 4]; aH[mf][3] = AsH[r0 + 8][k8 + tig + 4];
                aL[mf][0] = AsL[r0][k8 + tig];     aL[mf][1] = AsL[r0 + 8][k8 + tig];
                aL[mf][2] = AsL[r0][k8 + tig + 4]; aL[mf][3] = AsL[r0 + 8][k8 + tig + 4];
            }
#pragma unroll
            for (int nf = 0; nf < 4; nf++) {
                int cn = wn + nf * 8 + gid;
                bH[nf][0] = BsH[k8 + tig][cn]; bH[nf][1] = BsH[k8 + tig + 4][cn];
                bL[nf][0] = BsL[k8 + tig][cn]; bL[nf][1] = BsL[k8 + tig + 4][cn];
            }
#pragma unroll
            for (int mf = 0; mf < 2; mf++)
#pragma unroll
                for (int nf = 0; nf < 4; nf++) {
                    mma_tf32(acc[mf][nf], aH[mf], bH[nf]);
                    mma_tf32(acc[mf][nf], aH[mf], bL[nf]);
                    mma_tf32(acc[mf][nf], aL[mf], bH[nf]);
                }
        }
        __syncthreads();
    }

    // ---- epilogue ----
#pragma unroll
    for (int mf = 0; mf < 2; mf++) {
#pragma unroll
        for (int half = 0; half < 2; half++) {
            int mloc = wm + mf * 16 + gid + half * 8;
            int m = bm + mloc;
            const float* arow = addTbl ? (addTbl + (size_t)addIdx[m] * N4H) : nullptr;
            float* zrow = Z + (size_t)m * N4H;
#pragma unroll
            for (int nf = 0; nf < 4; nf++) {
                int cn = bn + wn + nf * 8 + tig * 2;
                float v0 = acc[mf][nf][half * 2 + 0];
                float v1 = acc[mf][nf][half * 2 + 1];
                if (bias) { v0 += bias[cn]; v1 += bias[cn + 1]; }
                if (arow) { v0 += arow[cn]; v1 += arow[cn + 1]; }
                float2 o; o.x = v0; o.y = v1;
                *(float2*)(zrow + cn) = o;
            }
        }
    }
}

// ---------------- LSTM cell (gates + masked state update) ----------------
__global__ void lstm_cell(const float* __restrict__ Z,
                          const int* __restrict__ maskSrc, int maskStride,
                          float* __restrict__ h, float* __restrict__ c)
{
    int i = blockIdx.x * blockDim.x + threadIdx.x;
    if (i >= B_ * H_) return;
    int m = i >> 10;
    int j = i & 1023;

    if (maskSrc[(size_t)m * maskStride] == 0) return;

    const float* zr = Z + (size_t)m * N4H;
    float zi = zr[j], zf = zr[1024 + j], zg = zr[2048 + j], zo = zr[3072 + j];

    float ig = 1.0f / (1.0f + expf(-zi));
    float fg = 1.0f / (1.0f + expf(-zf));
    float gg = tanhf(zg);
    float og = 1.0f / (1.0f + expf(-zo));

    float c2 = fg * c[i] + ig * gg;
    c[i] = c2;
    h[i] = og * tanhf(c2);
}

// ---------------- decoder output: logits + softmax + argmax ----------------
__global__ void dec_output(const float* __restrict__ h,
                           const float* __restrict__ outW, const float* __restrict__ outb,
                           float* __restrict__ out, int l,
                           int* __restrict__ tok, float* __restrict__ tokOut)
{
    const int ROWS = 4;
    __shared__ float hs[ROWS][H_];
    __shared__ float red[V_];
    __shared__ float smax, ssum;
    __shared__ int   sarg;

    int m0 = blockIdx.x * ROWS;
    int v  = threadIdx.x;

    for (int idx = threadIdx.x; idx < ROWS * H_; idx += blockDim.x) {
        int r = idx >> 10;
        hs[r][idx & 1023] = h[(size_t)(m0 + r) * H_ + (idx & 1023)];
    }
    __syncthreads();

    float acc[ROWS] = {0.f, 0.f, 0.f, 0.f};
#pragma unroll 8
    for (int k = 0; k < H_; k++) {
        float w = outW[(size_t)k * V_ + v];
#pragma unroll
        for (int r = 0; r < ROWS; r++) acc[r] += hs[r][k] * w;
    }
    float bb = outb[v];

    for (int r = 0; r < ROWS; r++) {
        float logit = acc[r] + bb;
        red[v] = logit;
        __syncthreads();
        if (v == 0) {
            float mx = red[0]; int am = 0;
            for (int q = 1; q < V_; q++) if (red[q] > mx) { mx = red[q]; am = q; }
            smax = mx; sarg = am;
        }
        __syncthreads();
        float e = expf(logit - smax);
        red[v] = e;
        __syncthreads();
        if (v == 0) {
            float s = 0.f;
            for (int q = 0; q < V_; q++) s += red[q];
            ssum = s;
        }
        __syncthreads();
        int m = m0 + r;
        out[(size_t)m * (L_ * V_) + (size_t)l * V_ + v] = e / ssum;
        if (v == 0) {
            tok[m] = sarg;
            if (tokOut) tokOut[(size_t)l * B_ + m] = (float)sarg;
        }
        __syncthreads();
    }
}

// ---------------- init ----------------
__global__ void init_state(float* __restrict__ h, float* __restrict__ c, int* __restrict__ tok)
{
    int i = blockIdx.x * blockDim.x + threadIdx.x;
    if (i < B_ * H_) { h[i] = 0.f; c[i] = 0.f; }
    if (i < B_) tok[i] = V_ - 1;
}

// ---------------- launch ----------------
extern "C" void kernel_launch(void* const* d_in, const int* in_sizes, int n_in,
                              void* d_out, int out_size)
{
    int base = 1;
    if (n_in >= 12 && in_sizes[1] == 1) base = 2;

    const int*   inputs  = (const int*)  d_in[0];
    const float* enc_emb = (const float*)d_in[base + 0];
    const float* enc_W   = (const float*)d_in[base + 1];
    const float* enc_U   = (const float*)d_in[base + 2];
    const float* enc_b   = (const float*)d_in[base + 3];
    const float* dec_emb = (const float*)d_in[base + 4];
    const float* dec_W   = (const float*)d_in[base + 5];
    const float* dec_U   = (const float*)d_in[base + 6];
    const float* dec_b   = (const float*)d_in[base + 7];
    const float* out_W   = (const float*)d_in[base + 8];
    const float* out_b   = (const float*)d_in[base + 9];
    float* out = (float*)d_out;

    float *p_h, *p_c, *p_z, *p_decEW;
    int* p_tok;
    cudaGetSymbolAddress((void**)&p_h, g_h);
    cudaGetSymbolAddress((void**)&p_c, g_c);
    cudaGetSymbolAddress((void**)&p_z, g_z);
    cudaGetSymbolAddress((void**)&p_decEW, g_decEW);
    cudaGetSymbolAddress((void**)&p_tok, g_tok);

    float* tokOut = nullptr;
    if (out_size >= B_ * L_ * V_ + L_ * B_) tokOut = out + (size_t)B_ * L_ * V_;

    init_state<<<(B_ * H_ + 255) / 256, 256>>>(p_h, p_c, p_tok);

    // one-time: dec_emb @ dec_W  (M = 128 rows)
    gemm_tc<<<dim3(N4H / BN, 1), 256>>>(
        dec_emb, dec_W, H_,
        nullptr, nullptr, 0, nullptr, 0,
        nullptr, nullptr, nullptr, p_decEW);

    dim3 gstep(N4H / BN, B_ / BM);   // 64 x 2 = 128 CTAs

    // ---- encoder ----
    for (int t = 0; t < T_; t++) {
        gemm_tc<<<gstep, 256>>>(
            p_h, enc_U, H_,
            enc_emb, inputs + t, T_, enc_W, H_,
            enc_b, nullptr, nullptr, p_z);
        lstm_cell<<<(B_ * H_ + 255) / 256, 256>>>(p_z, inputs + t, T_, p_h, p_c);
    }

    // ---- decoder ----
    for (int l = 0; l < L_; l++) {
        gemm_tc<<<gstep, 256>>>(
            p_h, dec_U, H_,
            nullptr, nullptr, 0, nullptr, 0,
            dec_b, p_decEW, p_tok, p_z);
        lstm_cell<<<(B_ * H_ + 255) / 256, 256>>>(p_z, p_tok, 1, p_h, p_c);
        dec_output<<<B_ / 4, V_>>>(p_h, out_W, out_b, out, l, p_tok, tokOut);
    }
}

// round 4
// speedup vs baseline: 1.4205x; 1.4205x over previous
#include <cuda_runtime.h>
#include <math.h>
#include <stdint.h>

#define B_   256
#define T_   64
#define H_   1024
#define V_   128
#define L_   32
#define N4H  4096

// ---- GEMM tiling ----
#define BM   128
#define BN   64
#define BKC  32              // K per chunk
#define AROW 36              // smem row stride (floats), conflict-free + 16B-aligned (144B)
#define ABUF (128 * AROW)    // 4608 floats per A buffer
#define BBUF (64 * AROW)     // 2304 floats per B buffer
#define OFF_AH   0
#define OFF_AL   (2 * ABUF)
#define OFF_BH   (4 * ABUF)
#define OFF_BL   (4 * ABUF + 2 * BBUF)
#define OFF_ROWS (4 * ABUF + 4 * BBUF)
#define SMEM_FLOATS (OFF_ROWS + 128)
#define SMEM_BYTES  (SMEM_FLOATS * 4)

// ---------------- persistent device scratch ----------------
__device__ float g_h[B_ * H_];
__device__ float g_c[B_ * H_];
__device__ float g_z[B_ * N4H];
__device__ float g_decEW[V_ * N4H];
__device__ int   g_tok[B_];
// A-side splits
__device__ float g_AH[B_ * H_];
__device__ float g_AL[B_ * H_];
__device__ float g_EH[V_ * H_];
__device__ float g_EL[V_ * H_];
__device__ float g_DEH[V_ * H_];
__device__ float g_DEL[V_ * H_];
// B-side (weights, transposed [n][k], tf32-split)
__device__ float g_BencH[(size_t)N4H * 2048];
__device__ float g_BencL[(size_t)N4H * 2048];
__device__ float g_BdecH[(size_t)N4H * H_];
__device__ float g_BdecL[(size_t)N4H * H_];
__device__ float g_BdwH[(size_t)N4H * H_];
__device__ float g_BdwL[(size_t)N4H * H_];

// ---------------- helpers ----------------
__device__ __forceinline__ void split_tf32(float x, float& hi, float& lo) {
    uint32_t u;
    asm("cvt.rna.tf32.f32 %0, %1;" : "=r"(u) : "f"(x));
    hi = __uint_as_float(u);
    uint32_t u2;
    float r = x - hi;
    asm("cvt.rna.tf32.f32 %0, %1;" : "=r"(u2) : "f"(r));
    lo = __uint_as_float(u2);
}

__device__ __forceinline__ void mma_tf32(float* d, const float* a, const float* b) {
    asm volatile(
        "mma.sync.aligned.m16n8k8.row.col.f32.tf32.tf32.f32 "
        "{%0,%1,%2,%3}, {%4,%5,%6,%7}, {%8,%9}, {%0,%1,%2,%3};"
        : "+f"(d[0]), "+f"(d[1]), "+f"(d[2]), "+f"(d[3])
        : "r"(__float_as_uint(a[0])), "r"(__float_as_uint(a[1])),
          "r"(__float_as_uint(a[2])), "r"(__float_as_uint(a[3])),
          "r"(__float_as_uint(b[0])), "r"(__float_as_uint(b[1])));
}

__device__ __forceinline__ void cpa16(uint32_t dst, const float* src) {
    asm volatile("cp.async.cg.shared.global [%0], [%1], 16;" :: "r"(dst), "l"(src) : "memory");
}
__device__ __forceinline__ void cpa_commit() {
    asm volatile("cp.async.commit_group;" ::: "memory");
}
template<int N> __device__ __forceinline__ void cpa_wait() {
    asm volatile("cp.async.wait_group %0;" :: "n"(N) : "memory");
}

// ---------------- pre-split kernels (once per launch) ----------------
// src [H_][4096] fp32  ->  dH/dL [4096][kStride] at column offset kOff (transposed, tf32-split)
__global__ void split_transpose(const float* __restrict__ src,
                                float* __restrict__ dH, float* __restrict__ dL,
                                int kOff, int kStride)
{
    __shared__ float tH[32][33];
    __shared__ float tL[32][33];
    int n0 = blockIdx.x * 32, k0 = blockIdx.y * 32;
    int tx = threadIdx.x, ty = threadIdx.y;   // 32 x 8
#pragma unroll
    for (int j = 0; j < 4; j++) {
        int k = ty + j * 8;
        float x = src[(size_t)(k0 + k) * N4H + n0 + tx];
        float hi, lo;
        split_tf32(x, hi, lo);
        tH[tx][k] = hi;
        tL[tx][k] = lo;
    }
    __syncthreads();
#pragma unroll
    for (int j = 0; j < 4; j++) {
        int n = ty + j * 8;
        size_t o = (size_t)(n0 + n) * kStride + kOff + k0 + tx;
        dH[o] = tH[n][tx];
        dL[o] = tL[n][tx];
    }
}

__global__ void split_rows(const float* __restrict__ src,
                           float* __restrict__ dH, float* __restrict__ dL, int n)
{
    int i = blockIdx.x * blockDim.x + threadIdx.x;
    if (i >= n) return;
    float hi, lo;
    split_tf32(src[i], hi, lo);
    dH[i] = hi;
    dL[i] = lo;
}

// ---------------- tf32-split tensor-core GEMM (pre-split operands) ----------------
// Z[m,n] = sum_k A0[bm+m,k] B[n,k]             (K0 cols, B k-offset 0)
//        + sum_k A1[rows_s[m],k] B[n,k+K0]     (K1 cols, gathered rows)
//        + bias[n] + addTbl[addIdx[m], n]
__global__ __launch_bounds__(256, 1)
void gemm_tc(const float* __restrict__ A0H, const float* __restrict__ A0L, int K0,
             const float* __restrict__ A1H, const float* __restrict__ A1L,
             const int* __restrict__ A1idx, int A1stride, int K1,
             const float* __restrict__ BH, const float* __restrict__ BL, int KB,
             const float* __restrict__ bias,
             const float* __restrict__ addTbl, const int* __restrict__ addIdx,
             float* __restrict__ Z)
{
    extern __shared__ float sm[];
    const int tid = threadIdx.x;
    const int wid = tid >> 5;
    const int lid = tid & 31;
    const int gid = lid >> 2;
    const int tig = lid & 3;
    const int bn  = blockIdx.x * BN;
    const int bm  = blockIdx.y * BM;
    const int wm  = (wid & 3) * 32;
    const int wn  = (wid >> 2) * 32;
    int* rows_s = (int*)(sm + OFF_ROWS);

    if (A1idx && tid < BM) rows_s[tid] = A1idx[(size_t)(bm + tid) * A1stride];
    __syncthreads();

    const int nch0 = K0 / BKC;
    const int nch  = nch0 + K1 / BKC;
    const uint32_t smb = (uint32_t)__cvta_generic_to_shared(sm);

    auto stage = [&](int buf, int cc) {
        const bool gath = cc >= nch0;
        const float* aH = gath ? A1H : A0H;
        const float* aL = gath ? A1L : A0L;
        const int kkA = (gath ? cc - nch0 : cc) * BKC;
        const int kkB = cc * BKC;
#pragma unroll
        for (int i = 0; i < 4; i++) {
            int idx = tid + i * 256;
            int r = idx >> 3, off = (idx & 7) * 4;
            int grow = gath ? rows_s[r] : (bm + r);
            size_t go = (size_t)grow * H_ + kkA + off;
            cpa16(smb + (uint32_t)(OFF_AH + buf * ABUF + r * AROW + off) * 4, aH + go);
            cpa16(smb + (uint32_t)(OFF_AL + buf * ABUF + r * AROW + off) * 4, aL + go);
        }
#pragma unroll
        for (int i = 0; i < 2; i++) {
            int idx = tid + i * 256;
            int n = idx >> 3, off = (idx & 7) * 4;
            size_t go = (size_t)(bn + n) * KB + kkB + off;
            cpa16(smb + (uint32_t)(OFF_BH + buf * BBUF + n * AROW + off) * 4, BH + go);
            cpa16(smb + (uint32_t)(OFF_BL + buf * BBUF + n * AROW + off) * 4, BL + go);
        }
        cpa_commit();
    };

    float acc[2][4][4];
#pragma unroll
    for (int mf = 0; mf < 2; mf++)
#pragma unroll
        for (int nf = 0; nf < 4; nf++)
#pragma unroll
            for (int q = 0; q < 4; q++) acc[mf][nf][q] = 0.f;

    stage(0, 0);

    for (int c = 0; c < nch; c++) {
        const int buf = c & 1;
        if (c + 1 < nch) { stage(buf ^ 1, c + 1); cpa_wait<1>(); }
        else             { cpa_wait<0>(); }
        __syncthreads();

        const float* sAH = sm + OFF_AH + buf * ABUF;
        const float* sAL = sm + OFF_AL + buf * ABUF;
        const float* sBH = sm + OFF_BH + buf * BBUF;
        const float* sBL = sm + OFF_BL + buf * BBUF;

#pragma unroll
        for (int k8 = 0; k8 < BKC; k8 += 8) {
            float aH[2][4], aL[2][4], bH[4][2], bL[4][2];
#pragma unroll
            for (int mf = 0; mf < 2; mf++) {
                int r0 = wm + mf * 16 + gid;
                aH[mf][0] = sAH[r0 * AROW + k8 + tig];
                aH[mf][1] = sAH[(r0 + 8) * AROW + k8 + tig];
                aH[mf][2] = sAH[r0 * AROW + k8 + tig + 4];
                aH[mf][3] = sAH[(r0 + 8) * AROW + k8 + tig + 4];
                aL[mf][0] = sAL[r0 * AROW + k8 + tig];
                aL[mf][1] = sAL[(r0 + 8) * AROW + k8 + tig];
                aL[mf][2] = sAL[r0 * AROW + k8 + tig + 4];
                aL[mf][3] = sAL[(r0 + 8) * AROW + k8 + tig + 4];
            }
#pragma unroll
            for (int nf = 0; nf < 4; nf++) {
                int cn = wn + nf * 8 + gid;
                bH[nf][0] = sBH[cn * AROW + k8 + tig];
                bH[nf][1] = sBH[cn * AROW + k8 + tig + 4];
                bL[nf][0] = sBL[cn * AROW + k8 + tig];
                bL[nf][1] = sBL[cn * AROW + k8 + tig + 4];
            }
#pragma unroll
            for (int mf = 0; mf < 2; mf++)
#pragma unroll
                for (int nf = 0; nf < 4; nf++) {
                    mma_tf32(acc[mf][nf], aH[mf], bH[nf]);
                    mma_tf32(acc[mf][nf], aH[mf], bL[nf]);
                    mma_tf32(acc[mf][nf], aL[mf], bH[nf]);
                }
        }
        __syncthreads();
    }

    // ---- epilogue ----
#pragma unroll
    for (int mf = 0; mf < 2; mf++) {
#pragma unroll
        for (int half = 0; half < 2; half++) {
            int m = bm + wm + mf * 16 + gid + half * 8;
            const float* arow = addTbl ? (addTbl + (size_t)addIdx[m] * N4H) : nullptr;
            float* zrow = Z + (size_t)m * N4H;
#pragma unroll
            for (int nf = 0; nf < 4; nf++) {
                int cn = bn + wn + nf * 8 + tig * 2;
                float v0 = acc[mf][nf][half * 2 + 0];
                float v1 = acc[mf][nf][half * 2 + 1];
                if (bias) { v0 += bias[cn]; v1 += bias[cn + 1]; }
                if (arow) { v0 += arow[cn]; v1 += arow[cn + 1]; }
                float2 o; o.x = v0; o.y = v1;
                *(float2*)(zrow + cn) = o;
            }
        }
    }
}

// ---------------- LSTM cell: gates + masked update + h-split emit ----------------
__global__ void lstm_cell(const float* __restrict__ Z,
                          const int* __restrict__ maskSrc, int maskStride,
                          float* __restrict__ h, float* __restrict__ c,
                          float* __restrict__ hH, float* __restrict__ hL)
{
    int i = blockIdx.x * blockDim.x + threadIdx.x;
    if (i >= B_ * H_) return;
    int m = i >> 10;
    int j = i & 1023;

    if (maskSrc[(size_t)m * maskStride] == 0) return;   // frozen: keep h, c, splits

    const float* zr = Z + (size_t)m * N4H;
    float zi = zr[j], zf = zr[1024 + j], zg = zr[2048 + j], zo = zr[3072 + j];

    float ig = 1.0f / (1.0f + expf(-zi));
    float fg = 1.0f / (1.0f + expf(-zf));
    float gg = tanhf(zg);
    float og = 1.0f / (1.0f + expf(-zo));

    float c2 = fg * c[i] + ig * gg;
    c[i] = c2;
    float h2 = og * tanhf(c2);
    h[i] = h2;
    float hi, lo;
    split_tf32(h2, hi, lo);
    hH[i] = hi;
    hL[i] = lo;
}

// ---------------- decoder output: logits + softmax + argmax ----------------
__global__ void dec_output(const float* __restrict__ h,
                           const float* __restrict__ outW, const float* __restrict__ outb,
                           float* __restrict__ out, int l,
                           int* __restrict__ tok, float* __restrict__ tokOut)
{
    const int ROWS = 4;
    __shared__ float hs[ROWS][H_];
    __shared__ float red[V_];
    __shared__ float smax, ssum;
    __shared__ int   sarg;

    int m0 = blockIdx.x * ROWS;
    int v  = threadIdx.x;

    for (int idx = threadIdx.x; idx < ROWS * H_; idx += blockDim.x) {
        int r = idx >> 10;
        hs[r][idx & 1023] = h[(size_t)(m0 + r) * H_ + (idx & 1023)];
    }
    __syncthreads();

    float acc[ROWS] = {0.f, 0.f, 0.f, 0.f};
#pragma unroll 8
    for (int k = 0; k < H_; k++) {
        float w = outW[(size_t)k * V_ + v];
#pragma unroll
        for (int r = 0; r < ROWS; r++) acc[r] += hs[r][k] * w;
    }
    float bb = outb[v];

    for (int r = 0; r < ROWS; r++) {
        float logit = acc[r] + bb;
        red[v] = logit;
        __syncthreads();
        if (v == 0) {
            float mx = red[0]; int am = 0;
            for (int q = 1; q < V_; q++) if (red[q] > mx) { mx = red[q]; am = q; }
            smax = mx; sarg = am;
        }
        __syncthreads();
        float e = expf(logit - smax);
        red[v] = e;
        __syncthreads();
        if (v == 0) {
            float s = 0.f;
            for (int q = 0; q < V_; q++) s += red[q];
            ssum = s;
        }
        __syncthreads();
        int m = m0 + r;
        out[(size_t)m * (L_ * V_) + (size_t)l * V_ + v] = e / ssum;
        if (v == 0) {
            tok[m] = sarg;
            if (tokOut) tokOut[(size_t)l * B_ + m] = (float)sarg;
        }
        __syncthreads();
    }
}

// ---------------- init ----------------
__global__ void init_state(float* __restrict__ h, float* __restrict__ c,
                           float* __restrict__ hH, float* __restrict__ hL,
                           int* __restrict__ tok)
{
    int i = blockIdx.x * blockDim.x + threadIdx.x;
    if (i < B_ * H_) { h[i] = 0.f; c[i] = 0.f; hH[i] = 0.f; hL[i] = 0.f; }
    if (i < B_) tok[i] = V_ - 1;
}

// ---------------- launch ----------------
extern "C" void kernel_launch(void* const* d_in, const int* in_sizes, int n_in,
                              void* d_out, int out_size)
{
    int base = 1;
    if (n_in >= 12 && in_sizes[1] == 1) base = 2;

    const int*   inputs  = (const int*)  d_in[0];
    const float* enc_emb = (const float*)d_in[base + 0];
    const float* enc_W   = (const float*)d_in[base + 1];
    const float* enc_U   = (const float*)d_in[base + 2];
    const float* enc_b   = (const float*)d_in[base + 3];
    const float* dec_emb = (const float*)d_in[base + 4];
    const float* dec_W   = (const float*)d_in[base + 5];
    const float* dec_U   = (const float*)d_in[base + 6];
    const float* dec_b   = (const float*)d_in[base + 7];
    const float* out_W   = (const float*)d_in[base + 8];
    const float* out_b   = (const float*)d_in[base + 9];
    float* out = (float*)d_out;

    float *p_h, *p_c, *p_z, *p_decEW, *p_AH, *p_AL, *p_EH, *p_EL, *p_DEH, *p_DEL;
    float *p_BeH, *p_BeL, *p_BdH, *p_BdL, *p_BwH, *p_BwL;
    int* p_tok;
    cudaGetSymbolAddress((void**)&p_h, g_h);
    cudaGetSymbolAddress((void**)&p_c, g_c);
    cudaGetSymbolAddress((void**)&p_z, g_z);
    cudaGetSymbolAddress((void**)&p_decEW, g_decEW);
    cudaGetSymbolAddress((void**)&p_tok, g_tok);
    cudaGetSymbolAddress((void**)&p_AH, g_AH);
    cudaGetSymbolAddress((void**)&p_AL, g_AL);
    cudaGetSymbolAddress((void**)&p_EH, g_EH);
    cudaGetSymbolAddress((void**)&p_EL, g_EL);
    cudaGetSymbolAddress((void**)&p_DEH, g_DEH);
    cudaGetSymbolAddress((void**)&p_DEL, g_DEL);
    cudaGetSymbolAddress((void**)&p_BeH, g_BencH);
    cudaGetSymbolAddress((void**)&p_BeL, g_BencL);
    cudaGetSymbolAddress((void**)&p_BdH, g_BdecH);
    cudaGetSymbolAddress((void**)&p_BdL, g_BdecL);
    cudaGetSymbolAddress((void**)&p_BwH, g_BdwH);
    cudaGetSymbolAddress((void**)&p_BwL, g_BdwL);

    float* tokOut = nullptr;
    if (out_size >= B_ * L_ * V_ + L_ * B_) tokOut = out + (size_t)B_ * L_ * V_;

    static int smem_set = 0;
    if (!smem_set) {
        cudaFuncSetAttribute(gemm_tc, cudaFuncAttributeMaxDynamicSharedMemorySize, SMEM_BYTES);
        smem_set = 1;
    }

    init_state<<<(B_ * H_ + 255) / 256, 256>>>(p_h, p_c, p_AH, p_AL, p_tok);

    // ---- one-time per launch: pre-split weights (transposed) and embeddings ----
    dim3 tg(N4H / 32, H_ / 32), tb(32, 8);
    split_transpose<<<tg, tb>>>(enc_U, p_BeH, p_BeL, 0,    2048);
    split_transpose<<<tg, tb>>>(enc_W, p_BeH, p_BeL, 1024, 2048);
    split_transpose<<<tg, tb>>>(dec_U, p_BdH, p_BdL, 0,    1024);
    split_transpose<<<tg, tb>>>(dec_W, p_BwH, p_BwL, 0,    1024);
    split_rows<<<(V_ * H_ + 255) / 256, 256>>>(enc_emb, p_EH, p_EL, V_ * H_);
    split_rows<<<(V_ * H_ + 255) / 256, 256>>>(dec_emb, p_DEH, p_DEL, V_ * H_);

    // decEW = dec_emb @ dec_W  (M = 128)
    gemm_tc<<<dim3(N4H / BN, 1), 256, SMEM_BYTES>>>(
        p_DEH, p_DEL, H_,
        nullptr, nullptr, nullptr, 0, 0,
        p_BwH, p_BwL, H_,
        nullptr, nullptr, nullptr, p_decEW);

    dim3 gstep(N4H / BN, B_ / BM);   // 64 x 2 = 128 CTAs

    // ---- encoder ----
    for (int t = 0; t < T_; t++) {
        gemm_tc<<<gstep, 256, SMEM_BYTES>>>(
            p_AH, p_AL, H_,
            p_EH, p_EL, inputs + t, T_, H_,
            p_BeH, p_BeL, 2048,
            enc_b, nullptr, nullptr, p_z);
        lstm_cell<<<(B_ * H_ + 255) / 256, 256>>>(p_z, inputs + t, T_, p_h, p_c, p_AH, p_AL);
    }

    // ---- decoder ----
    for (int l = 0; l < L_; l++) {
        gemm_tc<<<gstep, 256, SMEM_BYTES>>>(
            p_AH, p_AL, H_,
            nullptr, nullptr, nullptr, 0, 0,
            p_BdH, p_BdL, H_,
            dec_b, p_decEW, p_tok, p_z);
        lstm_cell<<<(B_ * H_ + 255) / 256, 256>>>(p_z, p_tok, 1, p_h, p_c, p_AH, p_AL);
        dec_output<<<B_ / 4, V_>>>(p_h, out_W, out_b, out, l, p_tok, tokOut);
    }
}

// round 5
// speedup vs baseline: 2.1944x; 1.5448x over previous
#include <cuda_runtime.h>
#include <math.h>
#include <stdint.h>

#define B_   256
#define T_   64
#define H_   1024
#define V_   128
#define L_   32
#define N4H  4096

// ---- GEMM tiling: CTA 128x64, 8 warps (warp 32x32), K=1024 in 32 chunks of 32 ----
#define NCH  32
#define ACH  4096            // A-blob floats per chunk image (128 rows x 32 k)
#define BCH  2048            // B-blob floats per chunk image (64 n x 32 k)
#define NSTAGE 4
#define STG_FLOATS (2*ACH + 2*BCH)     // 12288 (AH, AL, BH, BL)
#define SMEM_BYTES (NSTAGE * STG_FLOATS * 4)   // 196608

// ---------------- persistent device scratch ----------------
__device__ float g_h[B_ * H_];
__device__ float g_c[B_ * H_];
__device__ float g_z[B_ * N4H];
__device__ int   g_tok[B_];
// A-side blobs (mma-ready): [tile_m(2)][chunk(32)][4096]
__device__ float g_AH[B_ * H_];
__device__ float g_AL[B_ * H_];
// emb blob (one 128-row tile)
__device__ float g_EH[V_ * H_];
__device__ float g_EL[V_ * H_];
// Weight blobs (mma-ready): [tile_n(64)][chunk(32)][2048]
__device__ float g_BeH[(size_t)N4H * H_];
__device__ float g_BeL[(size_t)N4H * H_];
__device__ float g_BdH[(size_t)N4H * H_];
__device__ float g_BdL[(size_t)N4H * H_];
__device__ float g_BwH[(size_t)N4H * H_];
__device__ float g_BwL[(size_t)N4H * H_];
// Precomputed x-contribution tables (bias folded in)
__device__ float g_encEW[V_ * N4H];
__device__ float g_decEW[V_ * N4H];

// ---------------- helpers ----------------
__device__ __forceinline__ void split_tf32(float x, float& hi, float& lo) {
    uint32_t u;
    asm("cvt.rna.tf32.f32 %0, %1;" : "=r"(u) : "f"(x));
    hi = __uint_as_float(u);
    uint32_t u2;
    float r = x - hi;
    asm("cvt.rna.tf32.f32 %0, %1;" : "=r"(u2) : "f"(r));
    lo = __uint_as_float(u2);
}

__device__ __forceinline__ void mma_tf32(float* d, const float* a, const float* b) {
    asm volatile(
        "mma.sync.aligned.m16n8k8.row.col.f32.tf32.tf32.f32 "
        "{%0,%1,%2,%3}, {%4,%5,%6,%7}, {%8,%9}, {%0,%1,%2,%3};"
        : "+f"(d[0]), "+f"(d[1]), "+f"(d[2]), "+f"(d[3])
        : "r"(__float_as_uint(a[0])), "r"(__float_as_uint(a[1])),
          "r"(__float_as_uint(a[2])), "r"(__float_as_uint(a[3])),
          "r"(__float_as_uint(b[0])), "r"(__float_as_uint(b[1])));
}

__device__ __forceinline__ void cpa16(uint32_t dst, const float* src) {
    asm volatile("cp.async.cg.shared.global [%0], [%1], 16;" :: "r"(dst), "l"(src) : "memory");
}
__device__ __forceinline__ void cpa_commit() {
    asm volatile("cp.async.commit_group;" ::: "memory");
}
template<int N> __device__ __forceinline__ void cpa_wait() {
    asm volatile("cp.async.wait_group %0;" :: "n"(N) : "memory");
}

// Write one (m, m+8) x (j0..j0+7) group into the A blob (split on the fly).
// r0 = values of row m, r1 = row m+8.
__device__ __forceinline__ void write_Ablob(float* AH, float* AL, int m, int j0,
                                            const float* r0, const float* r1)
{
    int tile = m >> 7, chunk = j0 >> 5, wm_g = (m & 127) >> 5, k8 = (j0 & 31) >> 3;
    int mf = (m & 31) >> 4, gid = m & 7;
    size_t base = ((size_t)tile * NCH + chunk) * ACH + (size_t)(((wm_g * 4 + k8) * 2 + mf) * 128 + gid * 16);
#pragma unroll
    for (int tig = 0; tig < 4; tig++) {
        float4 h4, l4;
        split_tf32(r0[tig],     h4.x, l4.x);
        split_tf32(r1[tig],     h4.y, l4.y);
        split_tf32(r0[4 + tig], h4.z, l4.z);
        split_tf32(r1[4 + tig], h4.w, l4.w);
        *(float4*)(AH + base + tig * 4) = h4;
        *(float4*)(AL + base + tig * 4) = l4;
    }
}

// ---------------- weight split: W[1024][4096] -> mma-ready B blob ----------------
__global__ void split_weightB(const float* __restrict__ W,
                              float* __restrict__ BH, float* __restrict__ BL)
{
    __shared__ float sH[32][33];
    __shared__ float sL[32][33];
    int n0 = blockIdx.x * 32, k0 = blockIdx.y * 32;
    int tx = threadIdx.x & 31, ty = threadIdx.x >> 5;   // 32 x 8
#pragma unroll
    for (int i = 0; i < 4; i++) {
        int k = ty + i * 8;
        float x = W[(size_t)(k0 + k) * N4H + n0 + tx];
        float hi, lo;
        split_tf32(x, hi, lo);
        sH[k][tx] = hi;
        sL[k][tx] = lo;
    }
    __syncthreads();
    int tile_n = n0 >> 6, wn_g = (n0 >> 5) & 1, chunk = k0 >> 5;
    size_t obase = ((size_t)tile_n * NCH + chunk) * BCH + wn_g * 1024;
    int o4 = threadIdx.x;               // 0..255 float4 id
    int k8 = o4 >> 6, vh = (o4 >> 5) & 1, lane = o4 & 31;
    int gid = lane >> 2, tig = lane & 3;
    int n_a = (vh * 2 + 0) * 8 + gid;
    int n_b = (vh * 2 + 1) * 8 + gid;
    int k_a = k8 * 8 + tig;
    int k_b = k8 * 8 + 4 + tig;
    float4 vH, vL;
    vH.x = sH[k_a][n_a]; vH.y = sH[k_b][n_a]; vH.z = sH[k_a][n_b]; vH.w = sH[k_b][n_b];
    vL.x = sL[k_a][n_a]; vL.y = sL[k_b][n_a]; vL.z = sL[k_a][n_b]; vL.w = sL[k_b][n_b];
    *(float4*)(BH + obase + o4 * 4) = vH;
    *(float4*)(BL + obase + o4 * 4) = vL;
}

// ---------------- emb -> A blob (128 rows, tile 0) ----------------
__global__ void emb_blob(const float* __restrict__ emb,
                         float* __restrict__ AH, float* __restrict__ AL)
{
    int t = blockIdx.x * 256 + threadIdx.x;   // 0..8191
    if (t >= 8192) return;
    int mp = t >> 7;                          // 0..63
    int m  = ((mp >> 3) << 4) | (mp & 7);     // <128, bit3 = 0
    int j0 = (t & 127) << 3;
    float r0[8], r1[8];
    const float* p0 = emb + (size_t)m * H_ + j0;
    const float* p1 = emb + (size_t)(m + 8) * H_ + j0;
#pragma unroll
    for (int i = 0; i < 8; i++) { r0[i] = p0[i]; r1[i] = p1[i]; }
    write_Ablob(AH, AL, m, j0, r0, r1);
}

// ---------------- tensor-core step GEMM (mma-ready blobs) ----------------
// Z[m,n] = sum_k A[bm+m,k] * B[n,k]  + bias[n] + addTbl[addIdx[m*stride], n]
__global__ __launch_bounds__(256, 1)
void gemm_tc(const float* __restrict__ AH, const float* __restrict__ AL,
             const float* __restrict__ BH, const float* __restrict__ BL,
             const float* __restrict__ bias,
             const float* __restrict__ addTbl, const int* __restrict__ addIdx, int idxStride,
             float* __restrict__ Z)
{
    extern __shared__ float sm[];
    const int tid = threadIdx.x;
    const int wid = tid >> 5;
    const int lid = tid & 31;
    const int gid = lid >> 2;
    const int tig = lid & 3;
    const int bn  = blockIdx.x * 64;
    const int bm  = blockIdx.y * 128;
    const int wm_g = wid & 3;
    const int wn_g = wid >> 2;

    const float* AHt = AH + (size_t)blockIdx.y * NCH * ACH;
    const float* ALt = AL + (size_t)blockIdx.y * NCH * ACH;
    const float* BHt = BH + (size_t)blockIdx.x * NCH * BCH;
    const float* BLt = BL + (size_t)blockIdx.x * NCH * BCH;

    const uint32_t smb = (uint32_t)__cvta_generic_to_shared(sm);

    auto stage = [&](int s, int cc) {
        uint32_t d = smb + (uint32_t)s * (STG_FLOATS * 4);
        const float* aH = AHt + (size_t)cc * ACH;
        const float* aL = ALt + (size_t)cc * ACH;
        const float* bH = BHt + (size_t)cc * BCH;
        const float* bL = BLt + (size_t)cc * BCH;
#pragma unroll
        for (int i = 0; i < 4; i++) {
            int u = tid + i * 256;
            cpa16(d + u * 16,              aH + u * 4);
            cpa16(d + ACH * 4 + u * 16,    aL + u * 4);
        }
#pragma unroll
        for (int i = 0; i < 2; i++) {
            int u = tid + i * 256;
            cpa16(d + 2 * ACH * 4 + u * 16,             bH + u * 4);
            cpa16(d + (2 * ACH + BCH) * 4 + u * 16,     bL + u * 4);
        }
        cpa_commit();
    };

    float acc[2][4][4];
#pragma unroll
    for (int mf = 0; mf < 2; mf++)
#pragma unroll
        for (int nf = 0; nf < 4; nf++)
#pragma unroll
            for (int q = 0; q < 4; q++) acc[mf][nf][q] = 0.f;

    stage(0, 0); stage(1, 1); stage(2, 2);

    const int aoffB = (wm_g * 4) * 256 + lid * 4;
    const int boffB = (wn_g * 4) * 256 + lid * 4;

    for (int c = 0; c < NCH; c++) {
        const int s = c & 3;
        cpa_wait<2>();
        __syncthreads();
        if (c + 3 < NCH) stage((c + 3) & 3, c + 3);

        const float* sAH = sm + s * STG_FLOATS;
        const float* sAL = sAH + ACH;
        const float* sBH = sAH + 2 * ACH;
        const float* sBL = sAH + 2 * ACH + BCH;

#pragma unroll
        for (int k8 = 0; k8 < 4; k8++) {
            float4 ah0 = *(const float4*)(sAH + aoffB + k8 * 256);
            float4 ah1 = *(const float4*)(sAH + aoffB + k8 * 256 + 128);
            float4 al0 = *(const float4*)(sAL + aoffB + k8 * 256);
            float4 al1 = *(const float4*)(sAL + aoffB + k8 * 256 + 128);
            float4 bh0 = *(const float4*)(sBH + boffB + k8 * 256);
            float4 bh1 = *(const float4*)(sBH + boffB + k8 * 256 + 128);
            float4 bl0 = *(const float4*)(sBL + boffB + k8 * 256);
            float4 bl1 = *(const float4*)(sBL + boffB + k8 * 256 + 128);
            const float* aH0 = &ah0.x; const float* aH1 = &ah1.x;
            const float* aL0 = &al0.x; const float* aL1 = &al1.x;
            float bH[4][2] = {{bh0.x, bh0.y}, {bh0.z, bh0.w}, {bh1.x, bh1.y}, {bh1.z, bh1.w}};
            float bL[4][2] = {{bl0.x, bl0.y}, {bl0.z, bl0.w}, {bl1.x, bl1.y}, {bl1.z, bl1.w}};
#pragma unroll
            for (int nf = 0; nf < 4; nf++) {
                mma_tf32(acc[0][nf], aH0, bH[nf]);
                mma_tf32(acc[0][nf], aH0, bL[nf]);
                mma_tf32(acc[0][nf], aL0, bH[nf]);
                mma_tf32(acc[1][nf], aH1, bH[nf]);
                mma_tf32(acc[1][nf], aH1, bL[nf]);
                mma_tf32(acc[1][nf], aL1, bH[nf]);
            }
        }
    }

    // ---- epilogue ----
#pragma unroll
    for (int mf = 0; mf < 2; mf++) {
#pragma unroll
        for (int half = 0; half < 2; half++) {
            int m = bm + wm_g * 32 + mf * 16 + half * 8 + gid;
            const float* arow = addTbl ? (addTbl + (size_t)addIdx[(size_t)m * idxStride] * N4H) : nullptr;
            float* zrow = Z + (size_t)m * N4H;
#pragma unroll
            for (int nf = 0; nf < 4; nf++) {
                int cn = bn + wn_g * 32 + nf * 8 + tig * 2;
                float v0 = acc[mf][nf][half * 2 + 0];
                float v1 = acc[mf][nf][half * 2 + 1];
                if (bias) { v0 += bias[cn]; v1 += bias[cn + 1]; }
                if (arow) { v0 += arow[cn]; v1 += arow[cn + 1]; }
                float2 o; o.x = v0; o.y = v1;
                *(float2*)(zrow + cn) = o;
            }
        }
    }
}

// ---------------- LSTM cell: gates + masked update + blob h-split emit ----------------
__global__ void lstm_cell(const float* __restrict__ Z,
                          const int* __restrict__ maskSrc, int maskStride,
                          float* __restrict__ h, float* __restrict__ c,
                          float* __restrict__ AH, float* __restrict__ AL)
{
    int t = blockIdx.x * blockDim.x + threadIdx.x;   // 0..16383
    if (t >= 16384) return;
    int mp = t >> 7;                                 // 0..127
    int m  = ((mp >> 3) << 4) | (mp & 7);            // bit3 = 0, covers all m with pair m+8
    int j0 = (t & 127) << 3;

    float hv[2][8];
#pragma unroll
    for (int half = 0; half < 2; half++) {
        int mm = m + half * 8;
        bool act = maskSrc[(size_t)mm * maskStride] != 0;
        if (act) {
            const float* zr = Z + (size_t)mm * N4H + j0;
            float* cp = c + (size_t)mm * H_ + j0;
            float* hp = h + (size_t)mm * H_ + j0;
            float4 zi[2], zf[2], zg[2], zo[2], cc[2];
            zi[0] = *(const float4*)(zr);        zi[1] = *(const float4*)(zr + 4);
            zf[0] = *(const float4*)(zr + 1024); zf[1] = *(const float4*)(zr + 1028);
            zg[0] = *(const float4*)(zr + 2048); zg[1] = *(const float4*)(zr + 2052);
            zo[0] = *(const float4*)(zr + 3072); zo[1] = *(const float4*)(zr + 3076);
            cc[0] = *(const float4*)(cp);        cc[1] = *(const float4*)(cp + 4);
            float4 hout[2], cout[2];
#pragma unroll
            for (int q = 0; q < 8; q++) {
                float vi = ((const float*)&zi[q >> 2].x)[q & 3];
                float vf = ((const float*)&zf[q >> 2].x)[q & 3];
                float vg = ((const float*)&zg[q >> 2].x)[q & 3];
                float vo = ((const float*)&zo[q >> 2].x)[q & 3];
                float vc = ((const float*)&cc[q >> 2].x)[q & 3];
                float ig = 1.0f / (1.0f + expf(-vi));
                float fg = 1.0f / (1.0f + expf(-vf));
                float gg = tanhf(vg);
                float og = 1.0f / (1.0f + expf(-vo));
                float c2 = fg * vc + ig * gg;
                float h2 = og * tanhf(c2);
                ((float*)&cout[q >> 2].x)[q & 3] = c2;
                ((float*)&hout[q >> 2].x)[q & 3] = h2;
                hv[half][q] = h2;
            }
            *(float4*)(cp)     = cout[0];
            *(float4*)(cp + 4) = cout[1];
            *(float4*)(hp)     = hout[0];
            *(float4*)(hp + 4) = hout[1];
        } else {
            const float* hp = h + (size_t)mm * H_ + j0;
#pragma unroll
            for (int q = 0; q < 8; q++) hv[half][q] = hp[q];
        }
    }
    write_Ablob(AH, AL, m, j0, hv[0], hv[1]);
}

// ---------------- decoder output: logits + softmax + argmax ----------------
__global__ void dec_output(const float* __restrict__ h,
                           const float* __restrict__ outW, const float* __restrict__ outb,
                           float* __restrict__ out, int l,
                           int* __restrict__ tok, float* __restrict__ tokOut)
{
    const int ROWS = 4;
    __shared__ float hs[ROWS][H_];
    __shared__ float red[V_];
    __shared__ float smax, ssum;
    __shared__ int   sarg;

    int m0 = blockIdx.x * ROWS;
    int v  = threadIdx.x;

    for (int idx = threadIdx.x; idx < ROWS * H_; idx += blockDim.x) {
        int r = idx >> 10;
        hs[r][idx & 1023] = h[(size_t)(m0 + r) * H_ + (idx & 1023)];
    }
    __syncthreads();

    float acc[ROWS] = {0.f, 0.f, 0.f, 0.f};
#pragma unroll 8
    for (int k = 0; k < H_; k++) {
        float w = outW[(size_t)k * V_ + v];
#pragma unroll
        for (int r = 0; r < ROWS; r++) acc[r] += hs[r][k] * w;
    }
    float bb = outb[v];

    for (int r = 0; r < ROWS; r++) {
        float logit = acc[r] + bb;
        red[v] = logit;
        __syncthreads();
        if (v == 0) {
            float mx = red[0]; int am = 0;
            for (int q = 1; q < V_; q++) if (red[q] > mx) { mx = red[q]; am = q; }
            smax = mx; sarg = am;
        }
        __syncthreads();
        float e = expf(logit - smax);
        red[v] = e;
        __syncthreads();
        if (v == 0) {
            float s = 0.f;
            for (int q = 0; q < V_; q++) s += red[q];
            ssum = s;
        }
        __syncthreads();
        int m = m0 + r;
        out[(size_t)m * (L_ * V_) + (size_t)l * V_ + v] = e / ssum;
        if (v == 0) {
            tok[m] = sarg;
            if (tokOut) tokOut[(size_t)l * B_ + m] = (float)sarg;
        }
        __syncthreads();
    }
}

// ---------------- init ----------------
__global__ void init_state(float* __restrict__ h, float* __restrict__ c,
                           float* __restrict__ AH, float* __restrict__ AL,
                           int* __restrict__ tok)
{
    int i = blockIdx.x * blockDim.x + threadIdx.x;
    if (i < B_ * H_) { h[i] = 0.f; c[i] = 0.f; AH[i] = 0.f; AL[i] = 0.f; }
    if (i < B_) tok[i] = V_ - 1;
}

// ---------------- launch ----------------
extern "C" void kernel_launch(void* const* d_in, const int* in_sizes, int n_in,
                              void* d_out, int out_size)
{
    int base = 1;
    if (n_in >= 12 && in_sizes[1] == 1) base = 2;

    const int*   inputs  = (const int*)  d_in[0];
    const float* enc_emb = (const float*)d_in[base + 0];
    const float* enc_W   = (const float*)d_in[base + 1];
    const float* enc_U   = (const float*)d_in[base + 2];
    const float* enc_b   = (const float*)d_in[base + 3];
    const float* dec_emb = (const float*)d_in[base + 4];
    const float* dec_W   = (const float*)d_in[base + 5];
    const float* dec_U   = (const float*)d_in[base + 6];
    const float* dec_b   = (const float*)d_in[base + 7];
    const float* out_W   = (const float*)d_in[base + 8];
    const float* out_b   = (const float*)d_in[base + 9];
    float* out = (float*)d_out;

    float *p_h, *p_c, *p_z, *p_AH, *p_AL, *p_EH, *p_EL;
    float *p_BeH, *p_BeL, *p_BdH, *p_BdL, *p_BwH, *p_BwL, *p_encEW, *p_decEW;
    int* p_tok;
    cudaGetSymbolAddress((void**)&p_h, g_h);
    cudaGetSymbolAddress((void**)&p_c, g_c);
    cudaGetSymbolAddress((void**)&p_z, g_z);
    cudaGetSymbolAddress((void**)&p_tok, g_tok);
    cudaGetSymbolAddress((void**)&p_AH, g_AH);
    cudaGetSymbolAddress((void**)&p_AL, g_AL);
    cudaGetSymbolAddress((void**)&p_EH, g_EH);
    cudaGetSymbolAddress((void**)&p_EL, g_EL);
    cudaGetSymbolAddress((void**)&p_BeH, g_BeH);
    cudaGetSymbolAddress((void**)&p_BeL, g_BeL);
    cudaGetSymbolAddress((void**)&p_BdH, g_BdH);
    cudaGetSymbolAddress((void**)&p_BdL, g_BdL);
    cudaGetSymbolAddress((void**)&p_BwH, g_BwH);
    cudaGetSymbolAddress((void**)&p_BwL, g_BwL);
    cudaGetSymbolAddress((void**)&p_encEW, g_encEW);
    cudaGetSymbolAddress((void**)&p_decEW, g_decEW);

    float* tokOut = nullptr;
    if (out_size >= B_ * L_ * V_ + L_ * B_) tokOut = out + (size_t)B_ * L_ * V_;

    cudaFuncSetAttribute(gemm_tc, cudaFuncAttributeMaxDynamicSharedMemorySize, SMEM_BYTES);

    init_state<<<(B_ * H_ + 255) / 256, 256>>>(p_h, p_c, p_AH, p_AL, p_tok);

    dim3 wg(N4H / 32, H_ / 32);   // 128 x 32

    // ---- table builds ----
    // encEW = enc_emb @ enc_W + enc_b
    split_weightB<<<wg, 256>>>(enc_W, p_BwH, p_BwL);
    emb_blob<<<32, 256>>>(enc_emb, p_EH, p_EL);
    gemm_tc<<<dim3(64, 1), 256, SMEM_BYTES>>>(p_EH, p_EL, p_BwH, p_BwL,
                                              enc_b, nullptr, nullptr, 0, p_encEW);
    // decEW = dec_emb @ dec_W + dec_b
    split_weightB<<<wg, 256>>>(dec_W, p_BwH, p_BwL);
    emb_blob<<<32, 256>>>(dec_emb, p_EH, p_EL);
    gemm_tc<<<dim3(64, 1), 256, SMEM_BYTES>>>(p_EH, p_EL, p_BwH, p_BwL,
                                              dec_b, nullptr, nullptr, 0, p_decEW);
    // recurrent weights
    split_weightB<<<wg, 256>>>(enc_U, p_BeH, p_BeL);
    split_weightB<<<wg, 256>>>(dec_U, p_BdH, p_BdL);

    dim3 gstep(64, 2);   // 128 CTAs

    // ---- encoder ----
    for (int t = 0; t < T_; t++) {
        gemm_tc<<<gstep, 256, SMEM_BYTES>>>(p_AH, p_AL, p_BeH, p_BeL,
                                            nullptr, p_encEW, inputs + t, T_, p_z);
        lstm_cell<<<64, 256>>>(p_z, inputs + t, T_, p_h, p_c, p_AH, p_AL);
    }

    // ---- decoder ----
    for (int l = 0; l < L_; l++) {
        gemm_tc<<<gstep, 256, SMEM_BYTES>>>(p_AH, p_AL, p_BdH, p_BdL,
                                            nullptr, p_decEW, p_tok, 1, p_z);
        lstm_cell<<<64, 256>>>(p_z, p_tok, 1, p_h, p_c, p_AH, p_AL);
        dec_output<<<B_ / 4, V_>>>(p_h, out_W, out_b, out, l, p_tok, tokOut);
    }
}

// round 6
// speedup vs baseline: 2.2266x; 1.0147x over previous
#include <cuda_runtime.h>
#include <math.h>
#include <stdint.h>

#define B_   256
#define T_   64
#define H_   1024
#define V_   128
#define L_   32
#define N4H  4096

// ---- GEMM tiling: CTA 128x64, 8 warps (warp 32x32), K=1024 in 32 chunks of 32 ----
#define NCH  32
#define ACH  4096            // A-blob floats per chunk image (128 rows x 32 k)
#define BCH  2048            // B-blob floats per chunk image (64 n x 32 k)
#define NSTAGE 4
#define STG_FLOATS (2*ACH + 2*BCH)     // 12288 (AH, AL, BH, BL)
#define SMEM_BYTES (NSTAGE * STG_FLOATS * 4)   // 196608

// ---------------- persistent device scratch ----------------
__device__ float g_h[B_ * H_];
__device__ float g_c[B_ * H_];
__device__ float g_z[B_ * N4H];
__device__ int   g_tok[B_];
__device__ float g_AH[B_ * H_];
__device__ float g_AL[B_ * H_];
__device__ float g_EH[V_ * H_];
__device__ float g_EL[V_ * H_];
__device__ float g_BeH[(size_t)N4H * H_];
__device__ float g_BeL[(size_t)N4H * H_];
__device__ float g_BdH[(size_t)N4H * H_];
__device__ float g_BdL[(size_t)N4H * H_];
__device__ float g_BwH[(size_t)N4H * H_];
__device__ float g_BwL[(size_t)N4H * H_];
__device__ float g_encEW[V_ * N4H];
__device__ float g_decEW[V_ * N4H];

// ---------------- helpers ----------------
__device__ __forceinline__ void split_tf32(float x, float& hi, float& lo) {
    uint32_t u;
    asm("cvt.rna.tf32.f32 %0, %1;" : "=r"(u) : "f"(x));
    hi = __uint_as_float(u);
    uint32_t u2;
    float r = x - hi;
    asm("cvt.rna.tf32.f32 %0, %1;" : "=r"(u2) : "f"(r));
    lo = __uint_as_float(u2);
}

__device__ __forceinline__ void mma_tf32(float* d, const float* a, const float* b) {
    asm volatile(
        "mma.sync.aligned.m16n8k8.row.col.f32.tf32.tf32.f32 "
        "{%0,%1,%2,%3}, {%4,%5,%6,%7}, {%8,%9}, {%0,%1,%2,%3};"
        : "+f"(d[0]), "+f"(d[1]), "+f"(d[2]), "+f"(d[3])
        : "r"(__float_as_uint(a[0])), "r"(__float_as_uint(a[1])),
          "r"(__float_as_uint(a[2])), "r"(__float_as_uint(a[3])),
          "r"(__float_as_uint(b[0])), "r"(__float_as_uint(b[1])));
}

__device__ __forceinline__ void cpa16(uint32_t dst, const float* src) {
    asm volatile("cp.async.cg.shared.global [%0], [%1], 16;" :: "r"(dst), "l"(src) : "memory");
}
__device__ __forceinline__ void cpa_commit() {
    asm volatile("cp.async.commit_group;" ::: "memory");
}
template<int N> __device__ __forceinline__ void cpa_wait() {
    asm volatile("cp.async.wait_group %0;" :: "n"(N) : "memory");
}

// Write one (m, m+8) x (j0..j0+7) group into the A blob (split on the fly).
__device__ __forceinline__ void write_Ablob(float* AH, float* AL, int m, int j0,
                                            const float* r0, const float* r1)
{
    int tile = m >> 7, chunk = j0 >> 5, wm_g = (m & 127) >> 5, k8 = (j0 & 31) >> 3;
    int mf = (m & 31) >> 4, gid = m & 7;
    size_t base = ((size_t)tile * NCH + chunk) * ACH + (size_t)(((wm_g * 4 + k8) * 2 + mf) * 128 + gid * 16);
#pragma unroll
    for (int tig = 0; tig < 4; tig++) {
        float4 h4, l4;
        split_tf32(r0[tig],     h4.x, l4.x);
        split_tf32(r1[tig],     h4.y, l4.y);
        split_tf32(r0[4 + tig], h4.z, l4.z);
        split_tf32(r1[4 + tig], h4.w, l4.w);
        *(float4*)(AH + base + tig * 4) = h4;
        *(float4*)(AL + base + tig * 4) = l4;
    }
}

// ---------------- weight split: W[1024][4096] -> mma-ready B blob ----------------
__global__ void split_weightB(const float* __restrict__ W,
                              float* __restrict__ BH, float* __restrict__ BL)
{
    __shared__ float sH[32][33];
    __shared__ float sL[32][33];
    int n0 = blockIdx.x * 32, k0 = blockIdx.y * 32;
    int tx = threadIdx.x & 31, ty = threadIdx.x >> 5;
#pragma unroll
    for (int i = 0; i < 4; i++) {
        int k = ty + i * 8;
        float x = W[(size_t)(k0 + k) * N4H + n0 + tx];
        float hi, lo;
        split_tf32(x, hi, lo);
        sH[k][tx] = hi;
        sL[k][tx] = lo;
    }
    __syncthreads();
    int tile_n = n0 >> 6, wn_g = (n0 >> 5) & 1, chunk = k0 >> 5;
    size_t obase = ((size_t)tile_n * NCH + chunk) * BCH + wn_g * 1024;
    int o4 = threadIdx.x;
    int k8 = o4 >> 6, vh = (o4 >> 5) & 1, lane = o4 & 31;
    int gid = lane >> 2, tig = lane & 3;
    int n_a = (vh * 2 + 0) * 8 + gid;
    int n_b = (vh * 2 + 1) * 8 + gid;
    int k_a = k8 * 8 + tig;
    int k_b = k8 * 8 + 4 + tig;
    float4 vH, vL;
    vH.x = sH[k_a][n_a]; vH.y = sH[k_b][n_a]; vH.z = sH[k_a][n_b]; vH.w = sH[k_b][n_b];
    vL.x = sL[k_a][n_a]; vL.y = sL[k_b][n_a]; vL.z = sL[k_a][n_b]; vL.w = sL[k_b][n_b];
    *(float4*)(BH + obase + o4 * 4) = vH;
    *(float4*)(BL + obase + o4 * 4) = vL;
}

// ---------------- emb -> A blob (128 rows, tile 0) ----------------
__global__ void emb_blob(const float* __restrict__ emb,
                         float* __restrict__ AH, float* __restrict__ AL)
{
    int t = blockIdx.x * 256 + threadIdx.x;
    if (t >= 8192) return;
    int mp = t >> 7;
    int m  = ((mp >> 3) << 4) | (mp & 7);
    int j0 = (t & 127) << 3;
    float r0[8], r1[8];
    const float* p0 = emb + (size_t)m * H_ + j0;
    const float* p1 = emb + (size_t)(m + 8) * H_ + j0;
#pragma unroll
    for (int i = 0; i < 8; i++) { r0[i] = p0[i]; r1[i] = p1[i]; }
    write_Ablob(AH, AL, m, j0, r0, r1);
}

// ---------------- tensor-core step GEMM (mma-ready blobs, frag double-buffer) ----------------
__global__ __launch_bounds__(256, 1)
void gemm_tc(const float* __restrict__ AH, const float* __restrict__ AL,
             const float* __restrict__ BH, const float* __restrict__ BL,
             const float* __restrict__ bias,
             const float* __restrict__ addTbl, const int* __restrict__ addIdx, int idxStride,
             float* __restrict__ Z)
{
    extern __shared__ float sm[];
    const int tid = threadIdx.x;
    const int wid = tid >> 5;
    const int lid = tid & 31;
    const int gid = lid >> 2;
    const int tig = lid & 3;
    const int bn  = blockIdx.x * 64;
    const int bm  = blockIdx.y * 128;
    const int wm_g = wid & 3;
    const int wn_g = wid >> 2;

    const float* AHt = AH + (size_t)blockIdx.y * NCH * ACH;
    const float* ALt = AL + (size_t)blockIdx.y * NCH * ACH;
    const float* BHt = BH + (size_t)blockIdx.x * NCH * BCH;
    const float* BLt = BL + (size_t)blockIdx.x * NCH * BCH;

    const uint32_t smb = (uint32_t)__cvta_generic_to_shared(sm);

    auto stage = [&](int s, int cc) {
        uint32_t d = smb + (uint32_t)s * (STG_FLOATS * 4);
        const float* aH = AHt + (size_t)cc * ACH;
        const float* aL = ALt + (size_t)cc * ACH;
        const float* bH = BHt + (size_t)cc * BCH;
        const float* bL = BLt + (size_t)cc * BCH;
#pragma unroll
        for (int i = 0; i < 4; i++) {
            int u = tid + i * 256;
            cpa16(d + u * 16,              aH + u * 4);
            cpa16(d + ACH * 4 + u * 16,    aL + u * 4);
        }
#pragma unroll
        for (int i = 0; i < 2; i++) {
            int u = tid + i * 256;
            cpa16(d + 2 * ACH * 4 + u * 16,             bH + u * 4);
            cpa16(d + (2 * ACH + BCH) * 4 + u * 16,     bL + u * 4);
        }
        cpa_commit();
    };

    float acc[2][4][4];
#pragma unroll
    for (int mf = 0; mf < 2; mf++)
#pragma unroll
        for (int nf = 0; nf < 4; nf++)
#pragma unroll
            for (int q = 0; q < 4; q++) acc[mf][nf][q] = 0.f;

    stage(0, 0); stage(1, 1); stage(2, 2);

    const int aoffB = (wm_g * 4) * 256 + lid * 4;
    const int boffB = (wn_g * 4) * 256 + lid * 4;

    // fragment double buffers: [pb][ah0, ah1, al0, al1] / [pb][bh0, bh1, bl0, bl1]
    float4 fa[2][4], fb[2][4];

    for (int c = 0; c < NCH; c++) {
        const int s = c & 3;
        cpa_wait<2>();
        __syncthreads();
        if (c + 3 < NCH) stage((c + 3) & 3, c + 3);

        const float* sAH = sm + s * STG_FLOATS;
        const float* sAL = sAH + ACH;
        const float* sBH = sAH + 2 * ACH;
        const float* sBL = sAH + 2 * ACH + BCH;

        // preload k8 = 0 fragments
        fa[0][0] = *(const float4*)(sAH + aoffB);
        fa[0][1] = *(const float4*)(sAH + aoffB + 128);
        fa[0][2] = *(const float4*)(sAL + aoffB);
        fa[0][3] = *(const float4*)(sAL + aoffB + 128);
        fb[0][0] = *(const float4*)(sBH + boffB);
        fb[0][1] = *(const float4*)(sBH + boffB + 128);
        fb[0][2] = *(const float4*)(sBL + boffB);
        fb[0][3] = *(const float4*)(sBL + boffB + 128);

#pragma unroll
        for (int k8 = 0; k8 < 4; k8++) {
            const int cur = k8 & 1;
            const int nxt = cur ^ 1;
            if (k8 < 3) {
                int o = (k8 + 1) * 256;
                fa[nxt][0] = *(const float4*)(sAH + aoffB + o);
                fa[nxt][1] = *(const float4*)(sAH + aoffB + o + 128);
                fa[nxt][2] = *(const float4*)(sAL + aoffB + o);
                fa[nxt][3] = *(const float4*)(sAL + aoffB + o + 128);
                fb[nxt][0] = *(const float4*)(sBH + boffB + o);
                fb[nxt][1] = *(const float4*)(sBH + boffB + o + 128);
                fb[nxt][2] = *(const float4*)(sBL + boffB + o);
                fb[nxt][3] = *(const float4*)(sBL + boffB + o + 128);
            }
            const float* aH0 = (const float*)&fa[cur][0];
            const float* aH1 = (const float*)&fa[cur][1];
            const float* aL0 = (const float*)&fa[cur][2];
            const float* aL1 = (const float*)&fa[cur][3];
            float bH[4][2] = {{fb[cur][0].x, fb[cur][0].y}, {fb[cur][0].z, fb[cur][0].w},
                              {fb[cur][1].x, fb[cur][1].y}, {fb[cur][1].z, fb[cur][1].w}};
            float bL[4][2] = {{fb[cur][2].x, fb[cur][2].y}, {fb[cur][2].z, fb[cur][2].w},
                              {fb[cur][3].x, fb[cur][3].y}, {fb[cur][3].z, fb[cur][3].w}};
#pragma unroll
            for (int nf = 0; nf < 4; nf++) {
                mma_tf32(acc[0][nf], aH0, bH[nf]);
                mma_tf32(acc[0][nf], aH0, bL[nf]);
                mma_tf32(acc[0][nf], aL0, bH[nf]);
                mma_tf32(acc[1][nf], aH1, bH[nf]);
                mma_tf32(acc[1][nf], aH1, bL[nf]);
                mma_tf32(acc[1][nf], aL1, bH[nf]);
            }
        }
    }

    // ---- epilogue ----
#pragma unroll
    for (int mf = 0; mf < 2; mf++) {
#pragma unroll
        for (int half = 0; half < 2; half++) {
            int m = bm + wm_g * 32 + mf * 16 + half * 8 + gid;
            const float* arow = addTbl ? (addTbl + (size_t)addIdx[(size_t)m * idxStride] * N4H) : nullptr;
            float* zrow = Z + (size_t)m * N4H;
#pragma unroll
            for (int nf = 0; nf < 4; nf++) {
                int cn = bn + wn_g * 32 + nf * 8 + tig * 2;
                float v0 = acc[mf][nf][half * 2 + 0];
                float v1 = acc[mf][nf][half * 2 + 1];
                if (bias) { v0 += bias[cn]; v1 += bias[cn + 1]; }
                if (arow) { v0 += arow[cn]; v1 += arow[cn + 1]; }
                float2 o; o.x = v0; o.y = v1;
                *(float2*)(zrow + cn) = o;
            }
        }
    }
}

// ---------------- LSTM cell: gates + masked update + blob h-split emit ----------------
__global__ void lstm_cell(const float* __restrict__ Z,
                          const int* __restrict__ maskSrc, int maskStride,
                          float* __restrict__ h, float* __restrict__ c,
                          float* __restrict__ AH, float* __restrict__ AL)
{
    int t = blockIdx.x * blockDim.x + threadIdx.x;
    if (t >= 16384) return;
    int mp = t >> 7;
    int m  = ((mp >> 3) << 4) | (mp & 7);
    int j0 = (t & 127) << 3;

    float hv[2][8];
#pragma unroll
    for (int half = 0; half < 2; half++) {
        int mm = m + half * 8;
        bool act = maskSrc[(size_t)mm * maskStride] != 0;
        if (act) {
            const float* zr = Z + (size_t)mm * N4H + j0;
            float* cp = c + (size_t)mm * H_ + j0;
            float* hp = h + (size_t)mm * H_ + j0;
            float4 zi[2], zf[2], zg[2], zo[2], cc[2];
            zi[0] = *(const float4*)(zr);        zi[1] = *(const float4*)(zr + 4);
            zf[0] = *(const float4*)(zr + 1024); zf[1] = *(const float4*)(zr + 1028);
            zg[0] = *(const float4*)(zr + 2048); zg[1] = *(const float4*)(zr + 2052);
            zo[0] = *(const float4*)(zr + 3072); zo[1] = *(const float4*)(zr + 3076);
            cc[0] = *(const float4*)(cp);        cc[1] = *(const float4*)(cp + 4);
            float4 hout[2], cout[2];
#pragma unroll
            for (int q = 0; q < 8; q++) {
                float vi = ((const float*)&zi[q >> 2].x)[q & 3];
                float vf = ((const float*)&zf[q >> 2].x)[q & 3];
                float vg = ((const float*)&zg[q >> 2].x)[q & 3];
                float vo = ((const float*)&zo[q >> 2].x)[q & 3];
                float vc = ((const float*)&cc[q >> 2].x)[q & 3];
                float ig = 1.0f / (1.0f + expf(-vi));
                float fg = 1.0f / (1.0f + expf(-vf));
                float gg = tanhf(vg);
                float og = 1.0f / (1.0f + expf(-vo));
                float c2 = fg * vc + ig * gg;
                float h2 = og * tanhf(c2);
                ((float*)&cout[q >> 2].x)[q & 3] = c2;
                ((float*)&hout[q >> 2].x)[q & 3] = h2;
                hv[half][q] = h2;
            }
            *(float4*)(cp)     = cout[0];
            *(float4*)(cp + 4) = cout[1];
            *(float4*)(hp)     = hout[0];
            *(float4*)(hp + 4) = hout[1];
        } else {
            const float* hp = h + (size_t)mm * H_ + j0;
#pragma unroll
            for (int q = 0; q < 8; q++) hv[half][q] = hp[q];
        }
    }
    write_Ablob(AH, AL, m, j0, hv[0], hv[1]);
}

// ---------------- decoder output: logits + softmax + argmax ----------------
__global__ void dec_output(const float* __restrict__ h,
                           const float* __restrict__ outW, const float* __restrict__ outb,
                           float* __restrict__ out, int l,
                           int* __restrict__ tok, float* __restrict__ tokOut)
{
    const int ROWS = 4;
    __shared__ float hs[ROWS][H_];
    __shared__ float red[V_];
    __shared__ float smax, ssum;
    __shared__ int   sarg;

    int m0 = blockIdx.x * ROWS;
    int v  = threadIdx.x;

    for (int idx = threadIdx.x; idx < ROWS * H_; idx += blockDim.x) {
        int r = idx >> 10;
        hs[r][idx & 1023] = h[(size_t)(m0 + r) * H_ + (idx & 1023)];
    }
    __syncthreads();

    float acc[ROWS] = {0.f, 0.f, 0.f, 0.f};
#pragma unroll 8
    for (int k = 0; k < H_; k++) {
        float w = outW[(size_t)k * V_ + v];
#pragma unroll
        for (int r = 0; r < ROWS; r++) acc[r] += hs[r][k] * w;
    }
    float bb = outb[v];

    for (int r = 0; r < ROWS; r++) {
        float logit = acc[r] + bb;
        red[v] = logit;
        __syncthreads();
        if (v == 0) {
            float mx = red[0]; int am = 0;
            for (int q = 1; q < V_; q++) if (red[q] > mx) { mx = red[q]; am = q; }
            smax = mx; sarg = am;
        }
        __syncthreads();
        float e = expf(logit - smax);
        red[v] = e;
        __syncthreads();
        if (v == 0) {
            float s = 0.f;
            for (int q = 0; q < V_; q++) s += red[q];
            ssum = s;
        }
        __syncthreads();
        int m = m0 + r;
        out[(size_t)m * (L_ * V_) + (size_t)l * V_ + v] = e / ssum;
        if (v == 0) {
            tok[m] = sarg;
            if (tokOut) tokOut[(size_t)l * B_ + m] = (float)sarg;
        }
        __syncthreads();
    }
}

// ---------------- init ----------------
__global__ void init_state(float* __restrict__ h, float* __restrict__ c,
                           float* __restrict__ AH, float* __restrict__ AL,
                           int* __restrict__ tok)
{
    int i = blockIdx.x * blockDim.x + threadIdx.x;
    if (i < B_ * H_) { h[i] = 0.f; c[i] = 0.f; AH[i] = 0.f; AL[i] = 0.f; }
    if (i < B_) tok[i] = V_ - 1;
}

// ---------------- launch ----------------
extern "C" void kernel_launch(void* const* d_in, const int* in_sizes, int n_in,
                              void* d_out, int out_size)
{
    int base = 1;
    if (n_in >= 12 && in_sizes[1] == 1) base = 2;

    const int*   inputs  = (const int*)  d_in[0];
    const float* enc_emb = (const float*)d_in[base + 0];
    const float* enc_W   = (const float*)d_in[base + 1];
    const float* enc_U   = (const float*)d_in[base + 2];
    const float* enc_b   = (const float*)d_in[base + 3];
    const float* dec_emb = (const float*)d_in[base + 4];
    const float* dec_W   = (const float*)d_in[base + 5];
    const float* dec_U   = (const float*)d_in[base + 6];
    const float* dec_b   = (const float*)d_in[base + 7];
    const float* out_W   = (const float*)d_in[base + 8];
    const float* out_b   = (const float*)d_in[base + 9];
    float* out = (float*)d_out;

    float *p_h, *p_c, *p_z, *p_AH, *p_AL, *p_EH, *p_EL;
    float *p_BeH, *p_BeL, *p_BdH, *p_BdL, *p_BwH, *p_BwL, *p_encEW, *p_decEW;
    int* p_tok;
    cudaGetSymbolAddress((void**)&p_h, g_h);
    cudaGetSymbolAddress((void**)&p_c, g_c);
    cudaGetSymbolAddress((void**)&p_z, g_z);
    cudaGetSymbolAddress((void**)&p_tok, g_tok);
    cudaGetSymbolAddress((void**)&p_AH, g_AH);
    cudaGetSymbolAddress((void**)&p_AL, g_AL);
    cudaGetSymbolAddress((void**)&p_EH, g_EH);
    cudaGetSymbolAddress((void**)&p_EL, g_EL);
    cudaGetSymbolAddress((void**)&p_BeH, g_BeH);
    cudaGetSymbolAddress((void**)&p_BeL, g_BeL);
    cudaGetSymbolAddress((void**)&p_BdH, g_BdH);
    cudaGetSymbolAddress((void**)&p_BdL, g_BdL);
    cudaGetSymbolAddress((void**)&p_BwH, g_BwH);
    cudaGetSymbolAddress((void**)&p_BwL, g_BwL);
    cudaGetSymbolAddress((void**)&p_encEW, g_encEW);
    cudaGetSymbolAddress((void**)&p_decEW, g_decEW);

    float* tokOut = nullptr;
    if (out_size >= B_ * L_ * V_ + L_ * B_) tokOut = out + (size_t)B_ * L_ * V_;

    cudaFuncSetAttribute(gemm_tc, cudaFuncAttributeMaxDynamicSharedMemorySize, SMEM_BYTES);

    init_state<<<(B_ * H_ + 255) / 256, 256>>>(p_h, p_c, p_AH, p_AL, p_tok);

    dim3 wg(N4H / 32, H_ / 32);

    // ---- table builds ----
    split_weightB<<<wg, 256>>>(enc_W, p_BwH, p_BwL);
    emb_blob<<<32, 256>>>(enc_emb, p_EH, p_EL);
    gemm_tc<<<dim3(64, 1), 256, SMEM_BYTES>>>(p_EH, p_EL, p_BwH, p_BwL,
                                              enc_b, nullptr, nullptr, 0, p_encEW);
    split_weightB<<<wg, 256>>>(dec_W, p_BwH, p_BwL);
    emb_blob<<<32, 256>>>(dec_emb, p_EH, p_EL);
    gemm_tc<<<dim3(64, 1), 256, SMEM_BYTES>>>(p_EH, p_EL, p_BwH, p_BwL,
                                              dec_b, nullptr, nullptr, 0, p_decEW);
    split_weightB<<<wg, 256>>>(enc_U, p_BeH, p_BeL);
    split_weightB<<<wg, 256>>>(dec_U, p_BdH, p_BdL);

    dim3 gstep(64, 2);   // 128 CTAs

    // ---- encoder ----
    for (int t = 0; t < T_; t++) {
        gemm_tc<<<gstep, 256, SMEM_BYTES>>>(p_AH, p_AL, p_BeH, p_BeL,
                                            nullptr, p_encEW, inputs + t, T_, p_z);
        lstm_cell<<<64, 256>>>(p_z, inputs + t, T_, p_h, p_c, p_AH, p_AL);
    }

    // ---- decoder ----
    for (int l = 0; l < L_; l++) {
        gemm_tc<<<gstep, 256, SMEM_BYTES>>>(p_AH, p_AL, p_BdH, p_BdL,
                                            nullptr, p_decEW, p_tok, 1, p_z);
        lstm_cell<<<64, 256>>>(p_z, p_tok, 1, p_h, p_c, p_AH, p_AL);
        dec_output<<<B_ / 4, V_>>>(p_h, out_W, out_b, out, l, p_tok, tokOut);
    }
}

// round 7
// speedup vs baseline: 2.2289x; 1.0010x over previous
#include <cuda_runtime.h>
#include <math.h>
#include <stdint.h>

#define B_   256
#define T_   64
#define H_   1024
#define V_   128
#define L_   32
#define N4H  4096

// ---- GEMM tiling: CTA 128x64, 8 warps (warp 32x32), K=1024 in 32 chunks of 32 ----
#define NCH  32
#define ACH  4096
#define BCH  2048
#define NSTAGE 4
#define STG_FLOATS (2*ACH + 2*BCH)
#define SMEM_BYTES (NSTAGE * STG_FLOATS * 4)   // 196608

// ---------------- persistent device scratch ----------------
__device__ float g_h[B_ * H_];
__device__ float g_c[B_ * H_];
__device__ float g_z[B_ * N4H];
__device__ int   g_tok[B_];
__device__ float g_AH[B_ * H_];
__device__ float g_AL[B_ * H_];
__device__ float g_EH[V_ * H_];
__device__ float g_EL[V_ * H_];
__device__ float g_BeH[(size_t)N4H * H_];
__device__ float g_BeL[(size_t)N4H * H_];
__device__ float g_BdH[(size_t)N4H * H_];
__device__ float g_BdL[(size_t)N4H * H_];
__device__ float g_BwH[(size_t)N4H * H_];
__device__ float g_BwL[(size_t)N4H * H_];
__device__ float g_encEW[V_ * N4H];
__device__ float g_decEW[V_ * N4H];

// ---------------- helpers ----------------
__device__ __forceinline__ void split_tf32(float x, float& hi, float& lo) {
    uint32_t u;
    asm("cvt.rna.tf32.f32 %0, %1;" : "=r"(u) : "f"(x));
    hi = __uint_as_float(u);
    uint32_t u2;
    float r = x - hi;
    asm("cvt.rna.tf32.f32 %0, %1;" : "=r"(u2) : "f"(r));
    lo = __uint_as_float(u2);
}

__device__ __forceinline__ void mma_tf32(float* d, const float* a, const float* b) {
    asm volatile(
        "mma.sync.aligned.m16n8k8.row.col.f32.tf32.tf32.f32 "
        "{%0,%1,%2,%3}, {%4,%5,%6,%7}, {%8,%9}, {%0,%1,%2,%3};"
        : "+f"(d[0]), "+f"(d[1]), "+f"(d[2]), "+f"(d[3])
        : "r"(__float_as_uint(a[0])), "r"(__float_as_uint(a[1])),
          "r"(__float_as_uint(a[2])), "r"(__float_as_uint(a[3])),
          "r"(__float_as_uint(b[0])), "r"(__float_as_uint(b[1])));
}

__device__ __forceinline__ void cpa16(uint32_t dst, const float* src) {
    asm volatile("cp.async.cg.shared.global [%0], [%1], 16;" :: "r"(dst), "l"(src) : "memory");
}
__device__ __forceinline__ void cpa_commit() {
    asm volatile("cp.async.commit_group;" ::: "memory");
}
template<int N> __device__ __forceinline__ void cpa_wait() {
    asm volatile("cp.async.wait_group %0;" :: "n"(N) : "memory");
}

// Write one (m, m+8) x (j0..j0+7) group into the A blob (split on the fly).
__device__ __forceinline__ void write_Ablob(float* AH, float* AL, int m, int j0,
                                            const float* r0, const float* r1)
{
    int tile = m >> 7, chunk = j0 >> 5, wm_g = (m & 127) >> 5, k8 = (j0 & 31) >> 3;
    int mf = (m & 31) >> 4, gid = m & 7;
    size_t base = ((size_t)tile * NCH + chunk) * ACH + (size_t)(((wm_g * 4 + k8) * 2 + mf) * 128 + gid * 16);
#pragma unroll
    for (int tig = 0; tig < 4; tig++) {
        float4 h4, l4;
        split_tf32(r0[tig],     h4.x, l4.x);
        split_tf32(r1[tig],     h4.y, l4.y);
        split_tf32(r0[4 + tig], h4.z, l4.z);
        split_tf32(r1[4 + tig], h4.w, l4.w);
        *(float4*)(AH + base + tig * 4) = h4;
        *(float4*)(AL + base + tig * 4) = l4;
    }
}

// ---------------- weight split: W[1024][4096] -> mma-ready B blob ----------------
__global__ void split_weightB(const float* __restrict__ W,
                              float* __restrict__ BH, float* __restrict__ BL)
{
    __shared__ float sH[32][33];
    __shared__ float sL[32][33];
    int n0 = blockIdx.x * 32, k0 = blockIdx.y * 32;
    int tx = threadIdx.x & 31, ty = threadIdx.x >> 5;
#pragma unroll
    for (int i = 0; i < 4; i++) {
        int k = ty + i * 8;
        float x = W[(size_t)(k0 + k) * N4H + n0 + tx];
        float hi, lo;
        split_tf32(x, hi, lo);
        sH[k][tx] = hi;
        sL[k][tx] = lo;
    }
    __syncthreads();
    int tile_n = n0 >> 6, wn_g = (n0 >> 5) & 1, chunk = k0 >> 5;
    size_t obase = ((size_t)tile_n * NCH + chunk) * BCH + wn_g * 1024;
    int o4 = threadIdx.x;
    int k8 = o4 >> 6, vh = (o4 >> 5) & 1, lane = o4 & 31;
    int gid = lane >> 2, tig = lane & 3;
    int n_a = (vh * 2 + 0) * 8 + gid;
    int n_b = (vh * 2 + 1) * 8 + gid;
    int k_a = k8 * 8 + tig;
    int k_b = k8 * 8 + 4 + tig;
    float4 vH, vL;
    vH.x = sH[k_a][n_a]; vH.y = sH[k_b][n_a]; vH.z = sH[k_a][n_b]; vH.w = sH[k_b][n_b];
    vL.x = sL[k_a][n_a]; vL.y = sL[k_b][n_a]; vL.z = sL[k_a][n_b]; vL.w = sL[k_b][n_b];
    *(float4*)(BH + obase + o4 * 4) = vH;
    *(float4*)(BL + obase + o4 * 4) = vL;
}

// ---------------- emb -> A blob (128 rows, tile 0) ----------------
__global__ void emb_blob(const float* __restrict__ emb,
                         float* __restrict__ AH, float* __restrict__ AL)
{
    int t = blockIdx.x * 256 + threadIdx.x;
    if (t >= 8192) return;
    int mp = t >> 7;
    int m  = ((mp >> 3) << 4) | (mp & 7);
    int j0 = (t & 127) << 3;
    float r0[8], r1[8];
    const float* p0 = emb + (size_t)m * H_ + j0;
    const float* p1 = emb + (size_t)(m + 8) * H_ + j0;
#pragma unroll
    for (int i = 0; i < 8; i++) { r0[i] = p0[i]; r1[i] = p1[i]; }
    write_Ablob(AH, AL, m, j0, r0, r1);
}

// ---------------- tensor-core step GEMM (dependency-free MMA schedule) ----------------
__global__ __launch_bounds__(256, 1)
void gemm_tc(const float* __restrict__ AH, const float* __restrict__ AL,
             const float* __restrict__ BH, const float* __restrict__ BL,
             const float* __restrict__ bias,
             const float* __restrict__ addTbl, const int* __restrict__ addIdx, int idxStride,
             float* __restrict__ Z)
{
    extern __shared__ float sm[];
    const int tid = threadIdx.x;
    const int wid = tid >> 5;
    const int lid = tid & 31;
    const int gid = lid >> 2;
    const int tig = lid & 3;
    const int bn  = blockIdx.x * 64;
    const int bm  = blockIdx.y * 128;
    const int wm_g = wid & 3;
    const int wn_g = wid >> 2;

    const float* AHt = AH + (size_t)blockIdx.y * NCH * ACH;
    const float* ALt = AL + (size_t)blockIdx.y * NCH * ACH;
    const float* BHt = BH + (size_t)blockIdx.x * NCH * BCH;
    const float* BLt = BL + (size_t)blockIdx.x * NCH * BCH;

    const uint32_t smb = (uint32_t)__cvta_generic_to_shared(sm);

    auto stage = [&](int s, int cc) {
        uint32_t d = smb + (uint32_t)s * (STG_FLOATS * 4);
        const float* aH = AHt + (size_t)cc * ACH;
        const float* aL = ALt + (size_t)cc * ACH;
        const float* bH = BHt + (size_t)cc * BCH;
        const float* bL = BLt + (size_t)cc * BCH;
#pragma unroll
        for (int i = 0; i < 4; i++) {
            int u = tid + i * 256;
            cpa16(d + u * 16,              aH + u * 4);
            cpa16(d + ACH * 4 + u * 16,    aL + u * 4);
        }
#pragma unroll
        for (int i = 0; i < 2; i++) {
            int u = tid + i * 256;
            cpa16(d + 2 * ACH * 4 + u * 16,             bH + u * 4);
            cpa16(d + (2 * ACH + BCH) * 4 + u * 16,     bL + u * 4);
        }
        cpa_commit();
    };

    float acc[2][4][4];
#pragma unroll
    for (int mf = 0; mf < 2; mf++)
#pragma unroll
        for (int nf = 0; nf < 4; nf++)
#pragma unroll
            for (int q = 0; q < 4; q++) acc[mf][nf][q] = 0.f;

    stage(0, 0); stage(1, 1); stage(2, 2);

    const int aoffB = (wm_g * 4) * 256 + lid * 4;
    const int boffB = (wn_g * 4) * 256 + lid * 4;

    float4 fa[2][4], fb[2][4];

    for (int c = 0; c < NCH; c++) {
        const int s = c & 3;
        cpa_wait<2>();
        __syncthreads();
        if (c + 3 < NCH) stage((c + 3) & 3, c + 3);

        const float* sAH = sm + s * STG_FLOATS;
        const float* sAL = sAH + ACH;
        const float* sBH = sAH + 2 * ACH;
        const float* sBL = sAH + 2 * ACH + BCH;

        fa[0][0] = *(const float4*)(sAH + aoffB);
        fa[0][1] = *(const float4*)(sAH + aoffB + 128);
        fa[0][2] = *(const float4*)(sAL + aoffB);
        fa[0][3] = *(const float4*)(sAL + aoffB + 128);
        fb[0][0] = *(const float4*)(sBH + boffB);
        fb[0][1] = *(const float4*)(sBH + boffB + 128);
        fb[0][2] = *(const float4*)(sBL + boffB);
        fb[0][3] = *(const float4*)(sBL + boffB + 128);

#pragma unroll
        for (int k8 = 0; k8 < 4; k8++) {
            const int cur = k8 & 1;
            const int nxt = cur ^ 1;
            if (k8 < 3) {
                int o = (k8 + 1) * 256;
                fa[nxt][0] = *(const float4*)(sAH + aoffB + o);
                fa[nxt][1] = *(const float4*)(sAH + aoffB + o + 128);
                fa[nxt][2] = *(const float4*)(sAL + aoffB + o);
                fa[nxt][3] = *(const float4*)(sAL + aoffB + o + 128);
                fb[nxt][0] = *(const float4*)(sBH + boffB + o);
                fb[nxt][1] = *(const float4*)(sBH + boffB + o + 128);
                fb[nxt][2] = *(const float4*)(sBL + boffB + o);
                fb[nxt][3] = *(const float4*)(sBL + boffB + o + 128);
            }
            const float* aH0 = (const float*)&fa[cur][0];
            const float* aH1 = (const float*)&fa[cur][1];
            const float* aL0 = (const float*)&fa[cur][2];
            const float* aL1 = (const float*)&fa[cur][3];
            float bH[4][2] = {{fb[cur][0].x, fb[cur][0].y}, {fb[cur][0].z, fb[cur][0].w},
                              {fb[cur][1].x, fb[cur][1].y}, {fb[cur][1].z, fb[cur][1].w}};
            float bL[4][2] = {{fb[cur][2].x, fb[cur][2].y}, {fb[cur][2].z, fb[cur][2].w},
                              {fb[cur][3].x, fb[cur][3].y}, {fb[cur][3].z, fb[cur][3].w}};
            // Pass 1: HH — 8 distinct accumulators, no RAW stalls
#pragma unroll
            for (int nf = 0; nf < 4; nf++) {
                mma_tf32(acc[0][nf], aH0, bH[nf]);
                mma_tf32(acc[1][nf], aH1, bH[nf]);
            }
            // Pass 2: HL — each acc last touched 8 MMAs ago
#pragma unroll
            for (int nf = 0; nf < 4; nf++) {
                mma_tf32(acc[0][nf], aH0, bL[nf]);
                mma_tf32(acc[1][nf], aH1, bL[nf]);
            }
            // Pass 3: LH
#pragma unroll
            for (int nf = 0; nf < 4; nf++) {
                mma_tf32(acc[0][nf], aL0, bH[nf]);
                mma_tf32(acc[1][nf], aL1, bH[nf]);
            }
        }
    }

    // ---- epilogue ----
#pragma unroll
    for (int mf = 0; mf < 2; mf++) {
#pragma unroll
        for (int half = 0; half < 2; half++) {
            int m = bm + wm_g * 32 + mf * 16 + half * 8 + gid;
            const float* arow = addTbl ? (addTbl + (size_t)addIdx[(size_t)m * idxStride] * N4H) : nullptr;
            float* zrow = Z + (size_t)m * N4H;
#pragma unroll
            for (int nf = 0; nf < 4; nf++) {
                int cn = bn + wn_g * 32 + nf * 8 + tig * 2;
                float v0 = acc[mf][nf][half * 2 + 0];
                float v1 = acc[mf][nf][half * 2 + 1];
                if (bias) { v0 += bias[cn]; v1 += bias[cn + 1]; }
                if (arow) { v0 += arow[cn]; v1 += arow[cn + 1]; }
                float2 o; o.x = v0; o.y = v1;
                *(float2*)(zrow + cn) = o;
            }
        }
    }
}

// ---------------- LSTM cell: gates + masked update + blob h-split emit ----------------
__global__ void lstm_cell(const float* __restrict__ Z,
                          const int* __restrict__ maskSrc, int maskStride,
                          float* __restrict__ h, float* __restrict__ c,
                          float* __restrict__ AH, float* __restrict__ AL)
{
    int t = blockIdx.x * blockDim.x + threadIdx.x;
    if (t >= 16384) return;
    int mp = t >> 7;
    int m  = ((mp >> 3) << 4) | (mp & 7);
    int j0 = (t & 127) << 3;

    float hv[2][8];
#pragma unroll
    for (int half = 0; half < 2; half++) {
        int mm = m + half * 8;
        bool act = maskSrc[(size_t)mm * maskStride] != 0;
        if (act) {
            const float* zr = Z + (size_t)mm * N4H + j0;
            float* cp = c + (size_t)mm * H_ + j0;
            float* hp = h + (size_t)mm * H_ + j0;
            float4 zi[2], zf[2], zg[2], zo[2], cc[2];
            zi[0] = *(const float4*)(zr);        zi[1] = *(const float4*)(zr + 4);
            zf[0] = *(const float4*)(zr + 1024); zf[1] = *(const float4*)(zr + 1028);
            zg[0] = *(const float4*)(zr + 2048); zg[1] = *(const float4*)(zr + 2052);
            zo[0] = *(const float4*)(zr + 3072); zo[1] = *(const float4*)(zr + 3076);
            cc[0] = *(const float4*)(cp);        cc[1] = *(const float4*)(cp + 4);
            float4 hout[2], cout[2];
#pragma unroll
            for (int q = 0; q < 8; q++) {
                float vi = ((const float*)&zi[q >> 2].x)[q & 3];
                float vf = ((const float*)&zf[q >> 2].x)[q & 3];
                float vg = ((const float*)&zg[q >> 2].x)[q & 3];
                float vo = ((const float*)&zo[q >> 2].x)[q & 3];
                float vc = ((const float*)&cc[q >> 2].x)[q & 3];
                float ig = 1.0f / (1.0f + expf(-vi));
                float fg = 1.0f / (1.0f + expf(-vf));
                float gg = tanhf(vg);
                float og = 1.0f / (1.0f + expf(-vo));
                float c2 = fg * vc + ig * gg;
                float h2 = og * tanhf(c2);
                ((float*)&cout[q >> 2].x)[q & 3] = c2;
                ((float*)&hout[q >> 2].x)[q & 3] = h2;
                hv[half][q] = h2;
            }
            *(float4*)(cp)     = cout[0];
            *(float4*)(cp + 4) = cout[1];
            *(float4*)(hp)     = hout[0];
            *(float4*)(hp + 4) = hout[1];
        } else {
            const float* hp = h + (size_t)mm * H_ + j0;
#pragma unroll
            for (int q = 0; q < 8; q++) hv[half][q] = hp[q];
        }
    }
    write_Ablob(AH, AL, m, j0, hv[0], hv[1]);
}

// ---------------- decoder output: logits + softmax + argmax ----------------
__global__ void dec_output(const float* __restrict__ h,
                           const float* __restrict__ outW, const float* __restrict__ outb,
                           float* __restrict__ out, int l,
                           int* __restrict__ tok, float* __restrict__ tokOut)
{
    const int ROWS = 4;
    __shared__ float hs[ROWS][H_];
    __shared__ float red[V_];
    __shared__ float smax, ssum;
    __shared__ int   sarg;

    int m0 = blockIdx.x * ROWS;
    int v  = threadIdx.x;

    for (int idx = threadIdx.x; idx < ROWS * H_; idx += blockDim.x) {
        int r = idx >> 10;
        hs[r][idx & 1023] = h[(size_t)(m0 + r) * H_ + (idx & 1023)];
    }
    __syncthreads();

    float acc[ROWS] = {0.f, 0.f, 0.f, 0.f};
#pragma unroll 8
    for (int k = 0; k < H_; k++) {
        float w = outW[(size_t)k * V_ + v];
#pragma unroll
        for (int r = 0; r < ROWS; r++) acc[r] += hs[r][k] * w;
    }
    float bb = outb[v];

    for (int r = 0; r < ROWS; r++) {
        float logit = acc[r] + bb;
        red[v] = logit;
        __syncthreads();
        if (v == 0) {
            float mx = red[0]; int am = 0;
            for (int q = 1; q < V_; q++) if (red[q] > mx) { mx = red[q]; am = q; }
            smax = mx; sarg = am;
        }
        __syncthreads();
        float e = expf(logit - smax);
        red[v] = e;
        __syncthreads();
        if (v == 0) {
            float s = 0.f;
            for (int q = 0; q < V_; q++) s += red[q];
            ssum = s;
        }
        __syncthreads();
        int m = m0 + r;
        out[(size_t)m * (L_ * V_) + (size_t)l * V_ + v] = e / ssum;
        if (v == 0) {
            tok[m] = sarg;
            if (tokOut) tokOut[(size_t)l * B_ + m] = (float)sarg;
        }
        __syncthreads();
    }
}

// ---------------- init ----------------
__global__ void init_state(float* __restrict__ h, float* __restrict__ c,
                           float* __restrict__ AH, float* __restrict__ AL,
                           int* __restrict__ tok)
{
    int i = blockIdx.x * blockDim.x + threadIdx.x;
    if (i < B_ * H_) { h[i] = 0.f; c[i] = 0.f; AH[i] = 0.f; AL[i] = 0.f; }
    if (i < B_) tok[i] = V_ - 1;
}

// ---------------- launch ----------------
extern "C" void kernel_launch(void* const* d_in, const int* in_sizes, int n_in,
                              void* d_out, int out_size)
{
    int base = 1;
    if (n_in >= 12 && in_sizes[1] == 1) base = 2;

    const int*   inputs  = (const int*)  d_in[0];
    const float* enc_emb = (const float*)d_in[base + 0];
    const float* enc_W   = (const float*)d_in[base + 1];
    const float* enc_U   = (const float*)d_in[base + 2];
    const float* enc_b   = (const float*)d_in[base + 3];
    const float* dec_emb = (const float*)d_in[base + 4];
    const float* dec_W   = (const float*)d_in[base + 5];
    const float* dec_U   = (const float*)d_in[base + 6];
    const float* dec_b   = (const float*)d_in[base + 7];
    const float* out_W   = (const float*)d_in[base + 8];
    const float* out_b   = (const float*)d_in[base + 9];
    float* out = (float*)d_out;

    float *p_h, *p_c, *p_z, *p_AH, *p_AL, *p_EH, *p_EL;
    float *p_BeH, *p_BeL, *p_BdH, *p_BdL, *p_BwH, *p_BwL, *p_encEW, *p_decEW;
    int* p_tok;
    cudaGetSymbolAddress((void**)&p_h, g_h);
    cudaGetSymbolAddress((void**)&p_c, g_c);
    cudaGetSymbolAddress((void**)&p_z, g_z);
    cudaGetSymbolAddress((void**)&p_tok, g_tok);
    cudaGetSymbolAddress((void**)&p_AH, g_AH);
    cudaGetSymbolAddress((void**)&p_AL, g_AL);
    cudaGetSymbolAddress((void**)&p_EH, g_EH);
    cudaGetSymbolAddress((void**)&p_EL, g_EL);
    cudaGetSymbolAddress((void**)&p_BeH, g_BeH);
    cudaGetSymbolAddress((void**)&p_BeL, g_BeL);
    cudaGetSymbolAddress((void**)&p_BdH, g_BdH);
    cudaGetSymbolAddress((void**)&p_BdL, g_BdL);
    cudaGetSymbolAddress((void**)&p_BwH, g_BwH);
    cudaGetSymbolAddress((void**)&p_BwL, g_BwL);
    cudaGetSymbolAddress((void**)&p_encEW, g_encEW);
    cudaGetSymbolAddress((void**)&p_decEW, g_decEW);

    float* tokOut = nullptr;
    if (out_size >= B_ * L_ * V_ + L_ * B_) tokOut = out + (size_t)B_ * L_ * V_;

    cudaFuncSetAttribute(gemm_tc, cudaFuncAttributeMaxDynamicSharedMemorySize, SMEM_BYTES);

    init_state<<<(B_ * H_ + 255) / 256, 256>>>(p_h, p_c, p_AH, p_AL, p_tok);

    dim3 wg(N4H / 32, H_ / 32);

    // ---- table builds ----
    split_weightB<<<wg, 256>>>(enc_W, p_BwH, p_BwL);
    emb_blob<<<32, 256>>>(enc_emb, p_EH, p_EL);
    gemm_tc<<<dim3(64, 1), 256, SMEM_BYTES>>>(p_EH, p_EL, p_BwH, p_BwL,
                                              enc_b, nullptr, nullptr, 0, p_encEW);
    split_weightB<<<wg, 256>>>(dec_W, p_BwH, p_BwL);
    emb_blob<<<32, 256>>>(dec_emb, p_EH, p_EL);
    gemm_tc<<<dim3(64, 1), 256, SMEM_BYTES>>>(p_EH, p_EL, p_BwH, p_BwL,
                                              dec_b, nullptr, nullptr, 0, p_decEW);
    split_weightB<<<wg, 256>>>(enc_U, p_BeH, p_BeL);
    split_weightB<<<wg, 256>>>(dec_U, p_BdH, p_BdL);

    dim3 gstep(64, 2);   // 128 CTAs

    // ---- encoder ----
    for (int t = 0; t < T_; t++) {
        gemm_tc<<<gstep, 256, SMEM_BYTES>>>(p_AH, p_AL, p_BeH, p_BeL,
                                            nullptr, p_encEW, inputs + t, T_, p_z);
        lstm_cell<<<64, 256>>>(p_z, inputs + t, T_, p_h, p_c, p_AH, p_AL);
    }

    // ---- decoder ----
    for (int l = 0; l < L_; l++) {
        gemm_tc<<<gstep, 256, SMEM_BYTES>>>(p_AH, p_AL, p_BdH, p_BdL,
                                            nullptr, p_decEW, p_tok, 1, p_z);
        lstm_cell<<<64, 256>>>(p_z, p_tok, 1, p_h, p_c, p_AH, p_AL);
        dec_output<<<B_ / 4, V_>>>(p_h, out_W, out_b, out, l, p_tok, tokOut);
    }
}